// round 2
// baseline (speedup 1.0000x reference)
#include <cuda_runtime.h>
#include <cstddef>

// ImprovedGraphSAGE: 4x SAGEConv(aggr='lstm') fused pipeline.
// Layer l:  P = Xin @ Wih_l^T + (bih_l + bhh_l)            (p_kernel)
//           16-step LSTM over gathered P rows + H @ Whh^T   (lstm_kernel)
//           out = H @ Wl^T + bl + Xin @ Wr^T (+res)(relu)   (lstm_kernel epilogue)

#define NN       20000
#define DEG      16
#define FDIM     128
#define TM       48          // nodes per CTA
#define NTHREADS 384         // 16 (tx, output cols) x 24 (ty), 2 node rows/thread
#define NBLK     ((NN + TM - 1) / TM)   // 417
#define LDW      132         // padded SMEM leading dim for 128x128 weight tiles

// Scratch (device globals: runtime allocation is forbidden)
__device__ float g_P [(size_t)NN * 512];   // input-path gate pre-activations
__device__ float g_XA[(size_t)NN * FDIM];  // activation ping
__device__ float g_XB[(size_t)NN * FDIM];  // activation pong

#define SMEM_CORE ((size_t)(TM * FDIM + 128 * LDW) * 4)   // 92160 bytes
#define SMEM_P    SMEM_CORE
#define SMEM_L    (SMEM_CORE + 256)                        // + src staging

// ---------------------------------------------------------------------------
// accurate fast transcendentals (~1e-6 rel err; NOT tanh.approx)
__device__ __forceinline__ float fsig(float x) {
    float e, r;
    asm("ex2.approx.f32 %0, %1;" : "=f"(e) : "f"(-1.4426950408889634f * x));
    asm("rcp.approx.f32 %0, %1;" : "=f"(r) : "f"(1.0f + e));
    return r;
}
__device__ __forceinline__ float ftanh(float x) {
    return fmaf(2.0f, fsig(2.0f * x), -1.0f);
}

// ---------------------------------------------------------------------------
// acc[m][g] += sum_k sA[m][k]*sB[g][k], m in {m0,m0+1}, g in {ig*16+tx}.
__device__ __forceinline__ void gemm_48(const float* __restrict__ sA,
                                        const float* __restrict__ sB,
                                        float acc0[8], float acc1[8],
                                        int m0, int tx)
{
    #pragma unroll 4
    for (int k0 = 0; k0 < 128; k0 += 4) {
        const float4 a0 = *(const float4*)(sA + m0 * FDIM + k0);
        const float4 a1 = *(const float4*)(sA + (m0 + 1) * FDIM + k0);
        #pragma unroll
        for (int ig = 0; ig < 8; ig++) {
            const float4 b = *(const float4*)(sB + (ig * 16 + tx) * LDW + k0);
            acc0[ig] = fmaf(a0.x, b.x, acc0[ig]);
            acc0[ig] = fmaf(a0.y, b.y, acc0[ig]);
            acc0[ig] = fmaf(a0.z, b.z, acc0[ig]);
            acc0[ig] = fmaf(a0.w, b.w, acc0[ig]);
            acc1[ig] = fmaf(a1.x, b.x, acc1[ig]);
            acc1[ig] = fmaf(a1.y, b.y, acc1[ig]);
            acc1[ig] = fmaf(a1.z, b.z, acc1[ig]);
            acc1[ig] = fmaf(a1.w, b.w, acc1[ig]);
        }
    }
}

// ---------------------------------------------------------------------------
// P = Xin @ Wih^T + (bih + bhh).   Grid: (NBLK, 4): [48 nodes] x [128 cols].
__global__ void __launch_bounds__(NTHREADS)
p_kernel(const float* __restrict__ Xin,
         const float* __restrict__ Wih,    // [512,128]
         const float* __restrict__ bih,    // [512]
         const float* __restrict__ bhh)    // [512]
{
    extern __shared__ float sm[];
    float* sA = sm;                 // [TM][128]
    float* sB = sm + TM * FDIM;     // [128][LDW]

    const int tid = threadIdx.x;
    const int tx  = tid & 15;
    const int ty  = tid >> 4;
    const int m0  = ty * 2;
    const int n0  = blockIdx.x * TM;
    const int jb  = blockIdx.y * 128;

    for (int idx = tid; idx < TM * 32; idx += NTHREADS) {
        int r = idx >> 5, kq = idx & 31;
        int n = n0 + r; if (n >= NN) n = NN - 1;
        *(float4*)(sA + r * FDIM + kq * 4) =
            *(const float4*)(Xin + (size_t)n * FDIM + kq * 4);
    }
    {
        const float4* gw = (const float4*)(Wih + (size_t)jb * FDIM);
        for (int idx = tid; idx < 128 * 32; idx += NTHREADS) {
            int g = idx >> 5, kq = idx & 31;
            *(float4*)(sB + g * LDW + kq * 4) = gw[idx];
        }
    }
    __syncthreads();

    float acc0[8], acc1[8];
    #pragma unroll
    for (int j = 0; j < 8; j++) {
        int jc = j * 16 + tx;
        float bv = __ldg(bih + jb + jc) + __ldg(bhh + jb + jc);
        acc0[j] = bv; acc1[j] = bv;
    }
    gemm_48(sA, sB, acc0, acc1, m0, tx);

    const int nA = n0 + m0, nB = nA + 1;
    #pragma unroll
    for (int j = 0; j < 8; j++) {
        int jc = j * 16 + tx;
        if (nA < NN) g_P[(size_t)nA * 512 + jb + jc] = acc0[j];
        if (nB < NN) g_P[(size_t)nB * 512 + jb + jc] = acc1[j];
    }
}

// ---------------------------------------------------------------------------
// Fused 16-step LSTM + output projections. One CTA owns 48 nodes.
__global__ void __launch_bounds__(NTHREADS)
lstm_kernel(const float* __restrict__ Xin,   // [N,128]
            float* __restrict__ Xout,        // [N,outdim]
            const int* __restrict__ src,     // [E]
            const float* __restrict__ Whh,   // [512,128]
            const float* __restrict__ Wl,    // [outdim,128]
            const float* __restrict__ bl,    // [outdim]
            const float* __restrict__ Wr,    // [outdim,128]
            int outdim, int do_relu, int do_res)
{
    extern __shared__ float sm[];
    float* sH   = sm;                         // [TM][128]: h state, then X tile
    float* sW   = sm + TM * FDIM;             // [128][LDW]: streamed weights
    int*   sSrc = (int*)(sW + 128 * LDW);     // [TM]

    const int tid = threadIdx.x;
    const int tx  = tid & 15;
    const int ty  = tid >> 4;
    const int m0  = ty * 2;
    const int n0  = blockIdx.x * TM;

    for (int i = tid; i < TM * FDIM; i += NTHREADS) sH[i] = 0.0f;

    float c0[8], c1[8], si0[8], si1[8], sf0[8], sf1[8];
    #pragma unroll
    for (int j = 0; j < 8; j++) { c0[j] = 0.0f; c1[j] = 0.0f; }

    #pragma unroll 1
    for (int t = 0; t < DEG; t++) {
        #pragma unroll 1
        for (int qi = 0; qi < 4; qi++) {
            const int q = (qi < 2) ? (1 - qi) : qi;   // order f,i,g,o

            __syncthreads();   // prior chunk's sW readers done; sH writes visible
            {
                const float4* gw = (const float4*)(Whh + (size_t)q * 128 * FDIM);
                for (int idx = tid; idx < 128 * 32; idx += NTHREADS) {
                    int g = idx >> 5, kq = idx & 31;
                    *(float4*)(sW + g * LDW + kq * 4) = gw[idx];
                }
                if (qi == 0 && tid < TM) {
                    int n = n0 + tid;
                    sSrc[tid] = (n < NN) ? src[n * DEG + t] : 0;
                }
            }
            __syncthreads();

            float a0[8], a1[8];
            {
                const float* p0 = g_P + (size_t)sSrc[m0]     * 512 + q * 128;
                const float* p1 = g_P + (size_t)sSrc[m0 + 1] * 512 + q * 128;
                #pragma unroll
                for (int j = 0; j < 8; j++) {
                    a0[j] = __ldg(p0 + j * 16 + tx);
                    a1[j] = __ldg(p1 + j * 16 + tx);
                }
            }
            gemm_48(sH, sW, a0, a1, m0, tx);

            if (q == 1) {              // forget gate
                #pragma unroll
                for (int j = 0; j < 8; j++) { sf0[j] = fsig(a0[j]); sf1[j] = fsig(a1[j]); }
            } else if (q == 0) {       // input gate
                #pragma unroll
                for (int j = 0; j < 8; j++) { si0[j] = fsig(a0[j]); si1[j] = fsig(a1[j]); }
            } else if (q == 2) {       // candidate: c = sig(f)*c + sig(i)*tanh(g)
                #pragma unroll
                for (int j = 0; j < 8; j++) {
                    c0[j] = fmaf(sf0[j], c0[j], si0[j] * ftanh(a0[j]));
                    c1[j] = fmaf(sf1[j], c1[j], si1[j] * ftanh(a1[j]));
                }
            } else {                   // output gate: h = sig(o)*tanh(c)
                __syncthreads();       // all sH readers done before overwrite
                #pragma unroll
                for (int j = 0; j < 8; j++) {
                    sH[m0 * FDIM + j * 16 + tx]       = fsig(a0[j]) * ftanh(c0[j]);
                    sH[(m0 + 1) * FDIM + j * 16 + tx] = fsig(a1[j]) * ftanh(c1[j]);
                }
            }
        }
    }

    // ---- epilogue: out = H @ Wl^T + bl + X @ Wr^T (+res)(relu) --------------
    float o0[8], o1[8];
    #pragma unroll
    for (int j = 0; j < 8; j++) {
        int jc = j * 16 + tx;
        float bv = (jc < outdim) ? __ldg(bl + jc) : 0.0f;
        o0[j] = bv; o1[j] = bv;
    }

    __syncthreads();
    {   // load Wl (zero-pad rows >= outdim for layer 4)
        const float4* gw = (const float4*)Wl;
        const float4 z = make_float4(0.f, 0.f, 0.f, 0.f);
        for (int idx = tid; idx < 128 * 32; idx += NTHREADS) {
            int g = idx >> 5, kq = idx & 31;
            *(float4*)(sW + g * LDW + kq * 4) = (g < outdim) ? gw[idx] : z;
        }
    }
    __syncthreads();
    gemm_48(sH, sW, o0, o1, m0, tx);   // H @ Wl^T

    __syncthreads();
    {   // sH <- X tile, sW <- Wr
        for (int idx = tid; idx < TM * 32; idx += NTHREADS) {
            int r = idx >> 5, kq = idx & 31;
            int n = n0 + r; if (n >= NN) n = NN - 1;
            *(float4*)(sH + r * FDIM + kq * 4) =
                *(const float4*)(Xin + (size_t)n * FDIM + kq * 4);
        }
        const float4* gw = (const float4*)Wr;
        const float4 z = make_float4(0.f, 0.f, 0.f, 0.f);
        for (int idx = tid; idx < 128 * 32; idx += NTHREADS) {
            int g = idx >> 5, kq = idx & 31;
            *(float4*)(sW + g * LDW + kq * 4) = (g < outdim) ? gw[idx] : z;
        }
    }
    __syncthreads();
    gemm_48(sH, sW, o0, o1, m0, tx);   // += X @ Wr^T

    const int nA = n0 + m0, nB = nA + 1;
    #pragma unroll
    for (int j = 0; j < 8; j++) {
        int jc = j * 16 + tx;
        if (jc >= outdim) continue;
        float vA = o0[j], vB = o1[j];
        if (do_res) {   // residual = Xin (currently staged in sH)
            vA += sH[m0 * FDIM + jc];
            vB += sH[(m0 + 1) * FDIM + jc];
        }
        if (do_relu) { vA = fmaxf(vA, 0.0f); vB = fmaxf(vB, 0.0f); }
        if (nA < NN) Xout[(size_t)nA * outdim + jc] = vA;
        if (nB < NN) Xout[(size_t)nB * outdim + jc] = vB;
    }
}

// ---------------------------------------------------------------------------
static void run_layer(const float* Xin, float* Xout, const int* src,
                      const float* Wih, const float* Whh,
                      const float* bih, const float* bhh,
                      const float* Wl, const float* bl, const float* Wr,
                      int outdim, int do_relu, int do_res)
{
    p_kernel<<<dim3(NBLK, 4), NTHREADS, SMEM_P>>>(Xin, Wih, bih, bhh);
    lstm_kernel<<<NBLK, NTHREADS, SMEM_L>>>(Xin, Xout, src, Whh, Wl, bl, Wr,
                                            outdim, do_relu, do_res);
}

extern "C" void kernel_launch(void* const* d_in, const int* in_sizes, int n_in,
                              void* d_out, int out_size)
{
    (void)in_sizes; (void)n_in; (void)out_size;
    const float* x        = (const float*)d_in[0];
    const int*   src      = (const int*)  d_in[1];          // edge_index row 0
    const float* Wih      = (const float*)d_in[2];          // [4,512,128]
    const float* Whh      = (const float*)d_in[3];          // [4,512,128]
    const float* bih      = (const float*)d_in[4];          // [4,512]
    const float* bhh      = (const float*)d_in[5];          // [4,512]
    const float* Wl123    = (const float*)d_in[6];          // [3,128,128]
    const float* bl123    = (const float*)d_in[7];          // [3,128]
    const float* Wr123    = (const float*)d_in[8];          // [3,128,128]
    const float* Wl4      = (const float*)d_in[9];          // [64,128]
    const float* bl4      = (const float*)d_in[10];         // [64]
    const float* Wr4      = (const float*)d_in[11];         // [64,128]
    float*       out      = (float*)d_out;                  // [N,64]

    cudaFuncSetAttribute(p_kernel,
        cudaFuncAttributeMaxDynamicSharedMemorySize, (int)SMEM_P);
    cudaFuncSetAttribute(lstm_kernel,
        cudaFuncAttributeMaxDynamicSharedMemorySize, (int)SMEM_L);

    float *xa = nullptr, *xb = nullptr;
    cudaGetSymbolAddress((void**)&xa, g_XA);
    cudaGetSymbolAddress((void**)&xb, g_XB);

    // layer 1: x -> xa  (relu, no residual)
    run_layer(x,  xa, src, Wih + 0 * 512 * 128, Whh + 0 * 512 * 128,
              bih + 0 * 512, bhh + 0 * 512,
              Wl123 + 0 * 128 * 128, bl123 + 0 * 128, Wr123 + 0 * 128 * 128,
              128, 1, 0);
    // layer 2: xa -> xb (relu, residual)
    run_layer(xa, xb, src, Wih + 1 * 512 * 128, Whh + 1 * 512 * 128,
              bih + 1 * 512, bhh + 1 * 512,
              Wl123 + 1 * 128 * 128, bl123 + 1 * 128, Wr123 + 1 * 128 * 128,
              128, 1, 1);
    // layer 3: xb -> xa (relu, residual)
    run_layer(xb, xa, src, Wih + 2 * 512 * 128, Whh + 2 * 512 * 128,
              bih + 2 * 512, bhh + 2 * 512,
              Wl123 + 2 * 128 * 128, bl123 + 2 * 128, Wr123 + 2 * 128 * 128,
              128, 1, 1);
    // layer 4: xa -> out (no relu, no residual, OUT=64)
    run_layer(xa, out, src, Wih + 3 * 512 * 128, Whh + 3 * 512 * 128,
              bih + 3 * 512, bhh + 3 * 512,
              Wl4, bl4, Wr4,
              64, 0, 0);
}

// round 4
// speedup vs baseline: 3.1888x; 3.1888x over previous
#include <cuda_runtime.h>
#include <cuda_fp16.h>
#include <cstdint>
#include <cstddef>

// ============================================================================
// ImprovedGraphSAGE, tensor cores via portable mma.sync (no tcgen05 — the
// harness compiles for plain sm_100 where tcgen05 is unavailable).
//   p_kernel : P = Xin @ Wih^T + (bih+bhh)  (fp32 FFMA -> fp16 store)
//   lstm_mma : 16-step LSTM; H @ Whh^T on HMMA (fp16 in, fp32 acc); fused
//              projections H@Wl^T + bl + X@Wr^T (+res)(relu)
// ============================================================================

#define NN   20000
#define DEG  16
#define FDIM 128

// ---- p_kernel tiling (proven R2) ----
#define TM       48
#define NTHREADS 384
#define NBLK     ((NN + TM - 1) / TM)     // 417
#define LDW      132
#define SMEM_P   ((size_t)(TM * FDIM + 128 * LDW) * 4)

// ---- lstm mma kernel ----
#define MCTA    128                        // nodes per CTA
#define NCTA2   ((NN + MCTA - 1) / MCTA)   // 157
#define LTH     256                        // 8 warps
// fp16 tiles: row stride 136 halfs = 272 B (ldmatrix conflict-free)
#define TILE_B  34816                      // 128*272
#define SM_SRC  0                          // 128 ints
#define SM_H    1024
#define SM_W    (1024 + TILE_B)            // 4 slots (gates / Wl,Wr,X)
#define SMEM_L  (SM_W + 4 * TILE_B)        // 175104 B

__device__ __half g_P16[(size_t)NN * 512];
__device__ float  g_XA [(size_t)NN * FDIM];
__device__ float  g_XB [(size_t)NN * FDIM];

// ---------------------------------------------------------------------------
__device__ __forceinline__ uint32_t smem_u32(const void* p) {
    uint32_t a;
    asm("{ .reg .u64 t; cvta.to.shared.u64 t, %1; cvt.u32.u64 %0, t; }"
        : "=r"(a) : "l"(p));
    return a;
}
__device__ __forceinline__ void ldsm_x4(uint32_t a[4], uint32_t addr) {
    asm volatile("ldmatrix.sync.aligned.m8n8.x4.shared.b16 {%0,%1,%2,%3}, [%4];"
        : "=r"(a[0]), "=r"(a[1]), "=r"(a[2]), "=r"(a[3]) : "r"(addr));
}
__device__ __forceinline__ void ldsm_x2(uint32_t b[2], uint32_t addr) {
    asm volatile("ldmatrix.sync.aligned.m8n8.x2.shared.b16 {%0,%1}, [%2];"
        : "=r"(b[0]), "=r"(b[1]) : "r"(addr));
}
__device__ __forceinline__ void mma16816(float d[4], const uint32_t a[4],
                                         const uint32_t b[2]) {
    asm volatile("mma.sync.aligned.m16n8k16.row.col.f32.f16.f16.f32 "
        "{%0,%1,%2,%3}, {%4,%5,%6,%7}, {%8,%9}, {%0,%1,%2,%3};"
        : "+f"(d[0]), "+f"(d[1]), "+f"(d[2]), "+f"(d[3])
        : "r"(a[0]), "r"(a[1]), "r"(a[2]), "r"(a[3]), "r"(b[0]), "r"(b[1]));
}

// accurate fast transcendentals (~1e-6; NOT tanh.approx)
__device__ __forceinline__ float fsig(float x) {
    float e, r;
    asm("ex2.approx.f32 %0, %1;" : "=f"(e) : "f"(-1.4426950408889634f * x));
    asm("rcp.approx.f32 %0, %1;" : "=f"(r) : "f"(1.0f + e));
    return r;
}
__device__ __forceinline__ float ftanh(float x) {
    return fmaf(2.0f, fsig(2.0f * x), -1.0f);
}

// C[32x64] += A[32x128] * B[64x128]^T for this warp (8 k16 steps).
__device__ __forceinline__ void mma_gate(uint32_t aAddr, uint32_t bAddr,
                                         float acc[2][8][4]) {
    #pragma unroll
    for (int k0 = 0; k0 < 8; k0++) {
        uint32_t a0[4], a1[4];
        ldsm_x4(a0, aAddr + k0 * 32);
        ldsm_x4(a1, aAddr + 4352 + k0 * 32);   // +16 rows * 272
        #pragma unroll
        for (int nt = 0; nt < 8; nt++) {
            uint32_t b[2];
            ldsm_x2(b, bAddr + nt * 2176 + k0 * 32);  // +8 rows * 272
            mma16816(acc[0][nt], a0, b);
            mma16816(acc[1][nt], a1, b);
        }
    }
}

// init acc from gathered P rows (gcol = gate*128 + n0 + q*2)
__device__ __forceinline__ void loadP(float acc[2][8][4],
                                      int r00, int r01, int r10, int r11,
                                      int gcol) {
    const __half* p00 = g_P16 + (size_t)r00 * 512 + gcol;
    const __half* p01 = g_P16 + (size_t)r01 * 512 + gcol;
    const __half* p10 = g_P16 + (size_t)r10 * 512 + gcol;
    const __half* p11 = g_P16 + (size_t)r11 * 512 + gcol;
    #pragma unroll
    for (int nt = 0; nt < 8; nt++) {
        half2 v00 = __ldg((const half2*)(p00 + nt * 8));
        half2 v01 = __ldg((const half2*)(p01 + nt * 8));
        half2 v10 = __ldg((const half2*)(p10 + nt * 8));
        half2 v11 = __ldg((const half2*)(p11 + nt * 8));
        acc[0][nt][0] = __low2float(v00); acc[0][nt][1] = __high2float(v00);
        acc[0][nt][2] = __low2float(v01); acc[0][nt][3] = __high2float(v01);
        acc[1][nt][0] = __low2float(v10); acc[1][nt][1] = __high2float(v10);
        acc[1][nt][2] = __low2float(v11); acc[1][nt][3] = __high2float(v11);
    }
}

// ---------------------------------------------------------------------------
// p_kernel (FFMA, R2-proven), now storing fp16
// ---------------------------------------------------------------------------
__device__ __forceinline__ void gemm_48(const float* __restrict__ sA,
                                        const float* __restrict__ sB,
                                        float acc0[8], float acc1[8],
                                        int m0, int tx)
{
    #pragma unroll 4
    for (int k0 = 0; k0 < 128; k0 += 4) {
        const float4 a0 = *(const float4*)(sA + m0 * FDIM + k0);
        const float4 a1 = *(const float4*)(sA + (m0 + 1) * FDIM + k0);
        #pragma unroll
        for (int ig = 0; ig < 8; ig++) {
            const float4 b = *(const float4*)(sB + (ig * 16 + tx) * LDW + k0);
            acc0[ig] = fmaf(a0.x, b.x, acc0[ig]);
            acc0[ig] = fmaf(a0.y, b.y, acc0[ig]);
            acc0[ig] = fmaf(a0.z, b.z, acc0[ig]);
            acc0[ig] = fmaf(a0.w, b.w, acc0[ig]);
            acc1[ig] = fmaf(a1.x, b.x, acc1[ig]);
            acc1[ig] = fmaf(a1.y, b.y, acc1[ig]);
            acc1[ig] = fmaf(a1.z, b.z, acc1[ig]);
            acc1[ig] = fmaf(a1.w, b.w, acc1[ig]);
        }
    }
}

__global__ void __launch_bounds__(NTHREADS)
p_kernel(const float* __restrict__ Xin,
         const float* __restrict__ Wih,
         const float* __restrict__ bih,
         const float* __restrict__ bhh)
{
    extern __shared__ float sm[];
    float* sA = sm;
    float* sB = sm + TM * FDIM;

    const int tid = threadIdx.x;
    const int tx  = tid & 15;
    const int ty  = tid >> 4;
    const int m0  = ty * 2;
    const int n0  = blockIdx.x * TM;
    const int jb  = blockIdx.y * 128;

    for (int idx = tid; idx < TM * 32; idx += NTHREADS) {
        int r = idx >> 5, kq = idx & 31;
        int n = n0 + r; if (n >= NN) n = NN - 1;
        *(float4*)(sA + r * FDIM + kq * 4) =
            *(const float4*)(Xin + (size_t)n * FDIM + kq * 4);
    }
    {
        const float4* gw = (const float4*)(Wih + (size_t)jb * FDIM);
        for (int idx = tid; idx < 128 * 32; idx += NTHREADS) {
            int g = idx >> 5, kq = idx & 31;
            *(float4*)(sB + g * LDW + kq * 4) = gw[idx];
        }
    }
    __syncthreads();

    float acc0[8], acc1[8];
    #pragma unroll
    for (int j = 0; j < 8; j++) {
        int jc = j * 16 + tx;
        float bv = __ldg(bih + jb + jc) + __ldg(bhh + jb + jc);
        acc0[j] = bv; acc1[j] = bv;
    }
    gemm_48(sA, sB, acc0, acc1, m0, tx);

    const int nA = n0 + m0, nB = nA + 1;
    #pragma unroll
    for (int j = 0; j < 8; j++) {
        int jc = j * 16 + tx;
        if (nA < NN) g_P16[(size_t)nA * 512 + jb + jc] = __float2half_rn(acc0[j]);
        if (nB < NN) g_P16[(size_t)nB * 512 + jb + jc] = __float2half_rn(acc1[j]);
    }
}

// ---------------------------------------------------------------------------
// lstm_mma_kernel: CTA = 128 nodes, 8 warps; warp w: rows (w&3)*32..+31,
// gate-cols (w>>2)*64..+63. Gate processing order: i, g, f, o.
// ---------------------------------------------------------------------------
__global__ void __launch_bounds__(LTH, 1)
lstm_mma_kernel(const float* __restrict__ Xin,
                float* __restrict__ Xout,
                const int* __restrict__ src,
                const float* __restrict__ Whh,   // [512,128]
                const float* __restrict__ Wl,    // [outdim,128]
                const float* __restrict__ bl,    // [outdim]
                const float* __restrict__ Wr,    // [outdim,128]
                int outdim, int do_relu, int do_res)
{
    extern __shared__ char smc[];
    const uint32_t sb = smem_u32(smc);
    int* sSrc = (int*)(smc + SM_SRC);

    const int tid  = threadIdx.x;
    const int wid  = tid >> 5;
    const int lane = tid & 31;
    const int g8   = lane >> 2;
    const int q    = lane & 3;
    const int m0   = (wid & 3) * 32;
    const int n0   = (wid >> 2) * 64;
    const int nblk = blockIdx.x * MCTA;

    // ldmatrix base addresses
    const uint32_t aAddrH = sb + SM_H + (m0 + (lane & 15)) * 272 + ((lane >> 4) * 16);
    const uint32_t bOff   = (n0 + (lane & 7)) * 272 + (((lane >> 3) & 1) * 16);

    // ---- load all 4 Whh gate tiles fp32->fp16; zero H; stage src[t=0] -------
    for (int idx = tid; idx < 512 * 64; idx += LTH) {
        int rg = idx >> 6, cp = idx & 63;
        int gate = rg >> 7, row = rg & 127, col = cp * 2;
        float2 v = *(const float2*)(Whh + (size_t)rg * 128 + col);
        *(half2*)(smc + SM_W + gate * TILE_B + row * 272 + col * 2) =
            __float22half2_rn(v);
    }
    for (int idx = tid; idx < TILE_B / 16; idx += LTH)
        ((uint4*)(smc + SM_H))[idx] = make_uint4(0u, 0u, 0u, 0u);
    if (tid < MCTA) {
        int n = nblk + tid;
        sSrc[tid] = (n < NN) ? __ldg(src + n * DEG) : 0;
    }
    __syncthreads();

    float c[2][8][4];
    #pragma unroll
    for (int mt = 0; mt < 2; mt++)
        #pragma unroll
        for (int nt = 0; nt < 8; nt++)
            #pragma unroll
            for (int e = 0; e < 4; e++) c[mt][nt][e] = 0.0f;

    #pragma unroll 1
    for (int t = 0; t < DEG; t++) {
        const int r00 = sSrc[m0 + g8],      r01 = sSrc[m0 + g8 + 8];
        const int r10 = sSrc[m0 + g8 + 16], r11 = sSrc[m0 + g8 + 24];
        const int cq  = n0 + q * 2;

        float acc[2][8][4], tmp[2][8][4];

        // -- gate i (slot 0): tmp = sig(acc) --
        loadP(acc, r00, r01, r10, r11, 0 * 128 + cq);
        mma_gate(aAddrH, sb + SM_W + 0 * TILE_B + bOff, acc);
        #pragma unroll
        for (int mt = 0; mt < 2; mt++)
            #pragma unroll
            for (int nt = 0; nt < 8; nt++)
                #pragma unroll
                for (int e = 0; e < 4; e++)
                    tmp[mt][nt][e] = fsig(acc[mt][nt][e]);

        // -- gate g (slot 2): tmp *= tanh(acc) --
        loadP(acc, r00, r01, r10, r11, 2 * 128 + cq);
        mma_gate(aAddrH, sb + SM_W + 2 * TILE_B + bOff, acc);
        #pragma unroll
        for (int mt = 0; mt < 2; mt++)
            #pragma unroll
            for (int nt = 0; nt < 8; nt++)
                #pragma unroll
                for (int e = 0; e < 4; e++)
                    tmp[mt][nt][e] *= ftanh(acc[mt][nt][e]);

        // -- gate f (slot 1): c = sig(acc)*c + tmp --
        loadP(acc, r00, r01, r10, r11, 1 * 128 + cq);
        mma_gate(aAddrH, sb + SM_W + 1 * TILE_B + bOff, acc);
        #pragma unroll
        for (int mt = 0; mt < 2; mt++)
            #pragma unroll
            for (int nt = 0; nt < 8; nt++)
                #pragma unroll
                for (int e = 0; e < 4; e++)
                    c[mt][nt][e] = fmaf(fsig(acc[mt][nt][e]), c[mt][nt][e],
                                        tmp[mt][nt][e]);

        // -- gate o (slot 3): keep raw pre-activation in acc --
        loadP(acc, r00, r01, r10, r11, 3 * 128 + cq);
        mma_gate(aAddrH, sb + SM_W + 3 * TILE_B + bOff, acc);

        __syncthreads();   // every warp done READING sH this step

        // h = sig(o)*tanh(c) -> sH
        #pragma unroll
        for (int mt = 0; mt < 2; mt++) {
            const int row = m0 + mt * 16 + g8;
            #pragma unroll
            for (int nt = 0; nt < 8; nt++) {
                const int colb = (n0 + nt * 8 + q * 2) * 2;
                half2 h0 = __floats2half2_rn(
                    fsig(acc[mt][nt][0]) * ftanh(c[mt][nt][0]),
                    fsig(acc[mt][nt][1]) * ftanh(c[mt][nt][1]));
                half2 h1 = __floats2half2_rn(
                    fsig(acc[mt][nt][2]) * ftanh(c[mt][nt][2]),
                    fsig(acc[mt][nt][3]) * ftanh(c[mt][nt][3]));
                *(half2*)(smc + SM_H + row * 272 + colb)       = h0;
                *(half2*)(smc + SM_H + (row + 8) * 272 + colb) = h1;
            }
        }
        if (tid < MCTA && t + 1 < DEG) {
            int n = nblk + tid;
            sSrc[tid] = (n < NN) ? __ldg(src + n * DEG + t + 1) : 0;
        }
        __syncthreads();   // h(t) + sSrc(t+1) visible
    }

    // ---- projections: out = H@Wl^T + bl + X@Wr^T (+res)(relu) --------------
    // slot0 <- Wl, slot1 <- Wr (zero-padded rows>=outdim), slot2 <- X fp16
    {
        const half2 z = __float2half2_rn(0.0f);
        for (int idx = tid; idx < 128 * 64; idx += LTH) {
            int row = idx >> 6, cp = idx & 63, col = cp * 2;
            half2 vl = z, vr = z;
            if (row < outdim) {
                vl = __float22half2_rn(*(const float2*)(Wl + (size_t)row * 128 + col));
                vr = __float22half2_rn(*(const float2*)(Wr + (size_t)row * 128 + col));
            }
            int off = row * 272 + col * 2;
            *(half2*)(smc + SM_W + off)          = vl;
            *(half2*)(smc + SM_W + TILE_B + off) = vr;
            int n = nblk + row; if (n >= NN) n = NN - 1;
            *(half2*)(smc + SM_W + 2 * TILE_B + off) =
                __float22half2_rn(*(const float2*)(Xin + (size_t)n * 128 + col));
        }
    }
    __syncthreads();

    float acc[2][8][4];
    #pragma unroll
    for (int mt = 0; mt < 2; mt++) {
        const int row0  = m0 + mt * 16 + g8;
        const int node0 = nblk + row0, node1 = node0 + 8;
        #pragma unroll
        for (int nt = 0; nt < 8; nt++) {
            const int colp = n0 + nt * 8 + q * 2;
            float b0 = 0.f, b1 = 0.f;
            if (colp < outdim) { b0 = __ldg(bl + colp); b1 = __ldg(bl + colp + 1); }
            float x00 = 0.f, x01 = 0.f, x10 = 0.f, x11 = 0.f;
            if (do_res) {
                if (node0 < NN) {
                    float2 v = *(const float2*)(Xin + (size_t)node0 * 128 + colp);
                    x00 = v.x; x01 = v.y;
                }
                if (node1 < NN) {
                    float2 v = *(const float2*)(Xin + (size_t)node1 * 128 + colp);
                    x10 = v.x; x11 = v.y;
                }
            }
            acc[mt][nt][0] = b0 + x00; acc[mt][nt][1] = b1 + x01;
            acc[mt][nt][2] = b0 + x10; acc[mt][nt][3] = b1 + x11;
        }
    }

    const uint32_t aAddrX = sb + SM_W + 2 * TILE_B +
                            (m0 + (lane & 15)) * 272 + ((lane >> 4) * 16);
    mma_gate(aAddrH, sb + SM_W + 0 * TILE_B + bOff, acc);   // H @ Wl^T
    mma_gate(aAddrX, sb + SM_W + 1 * TILE_B + bOff, acc);   // X @ Wr^T

    #pragma unroll
    for (int mt = 0; mt < 2; mt++) {
        const int row0  = m0 + mt * 16 + g8;
        const int node0 = nblk + row0, node1 = node0 + 8;
        #pragma unroll
        for (int nt = 0; nt < 8; nt++) {
            const int colp = n0 + nt * 8 + q * 2;
            if (colp >= outdim) continue;
            float v0 = acc[mt][nt][0], v1 = acc[mt][nt][1];
            float v2 = acc[mt][nt][2], v3 = acc[mt][nt][3];
            if (do_relu) {
                v0 = fmaxf(v0, 0.f); v1 = fmaxf(v1, 0.f);
                v2 = fmaxf(v2, 0.f); v3 = fmaxf(v3, 0.f);
            }
            if (node0 < NN)
                *(float2*)(Xout + (size_t)node0 * outdim + colp) = make_float2(v0, v1);
            if (node1 < NN)
                *(float2*)(Xout + (size_t)node1 * outdim + colp) = make_float2(v2, v3);
        }
    }
}

// ---------------------------------------------------------------------------
static void run_layer(const float* Xin, float* Xout, const int* src,
                      const float* Wih, const float* Whh,
                      const float* bih, const float* bhh,
                      const float* Wl, const float* bl, const float* Wr,
                      int outdim, int do_relu, int do_res)
{
    p_kernel<<<dim3(NBLK, 4), NTHREADS, SMEM_P>>>(Xin, Wih, bih, bhh);
    lstm_mma_kernel<<<NCTA2, LTH, SMEM_L>>>(Xin, Xout, src, Whh, Wl, bl, Wr,
                                            outdim, do_relu, do_res);
}

extern "C" void kernel_launch(void* const* d_in, const int* in_sizes, int n_in,
                              void* d_out, int out_size)
{
    (void)in_sizes; (void)n_in; (void)out_size;
    const float* x     = (const float*)d_in[0];
    const int*   src   = (const int*)  d_in[1];
    const float* Wih   = (const float*)d_in[2];   // [4,512,128]
    const float* Whh   = (const float*)d_in[3];   // [4,512,128]
    const float* bih   = (const float*)d_in[4];   // [4,512]
    const float* bhh   = (const float*)d_in[5];   // [4,512]
    const float* Wl123 = (const float*)d_in[6];   // [3,128,128]
    const float* bl123 = (const float*)d_in[7];   // [3,128]
    const float* Wr123 = (const float*)d_in[8];   // [3,128,128]
    const float* Wl4   = (const float*)d_in[9];   // [64,128]
    const float* bl4   = (const float*)d_in[10];  // [64]
    const float* Wr4   = (const float*)d_in[11];  // [64,128]
    float*       out   = (float*)d_out;           // [N,64]

    cudaFuncSetAttribute(p_kernel,
        cudaFuncAttributeMaxDynamicSharedMemorySize, (int)SMEM_P);
    cudaFuncSetAttribute(lstm_mma_kernel,
        cudaFuncAttributeMaxDynamicSharedMemorySize, (int)SMEM_L);

    float *xa = nullptr, *xb = nullptr;
    cudaGetSymbolAddress((void**)&xa, g_XA);
    cudaGetSymbolAddress((void**)&xb, g_XB);

    run_layer(x,  xa, src, Wih + 0 * 512 * 128, Whh + 0 * 512 * 128,
              bih + 0 * 512, bhh + 0 * 512,
              Wl123 + 0 * 128 * 128, bl123 + 0 * 128, Wr123 + 0 * 128 * 128,
              128, 1, 0);
    run_layer(xa, xb, src, Wih + 1 * 512 * 128, Whh + 1 * 512 * 128,
              bih + 1 * 512, bhh + 1 * 512,
              Wl123 + 1 * 128 * 128, bl123 + 1 * 128, Wr123 + 1 * 128 * 128,
              128, 1, 1);
    run_layer(xb, xa, src, Wih + 2 * 512 * 128, Whh + 2 * 512 * 128,
              bih + 2 * 512, bhh + 2 * 512,
              Wl123 + 2 * 128 * 128, bl123 + 2 * 128, Wr123 + 2 * 128 * 128,
              128, 1, 1);
    run_layer(xa, out, src, Wih + 3 * 512 * 128, Whh + 3 * 512 * 128,
              bih + 3 * 512, bhh + 3 * 512,
              Wl4, bl4, Wr4,
              64, 0, 0);
}

// round 5
// speedup vs baseline: 3.9673x; 1.2441x over previous
#include <cuda_runtime.h>
#include <cuda_fp16.h>
#include <cstdint>
#include <cstddef>

// ============================================================================
// ImprovedGraphSAGE via portable mma.sync (HMMA) — sm_100-safe (no tcgen05).
//   p_kernel : P = Xin @ Wih^T + (bih+bhh)  (fp32 FFMA -> fp16 store)
//   lstm_mma : 16-step LSTM; H @ Whh^T on HMMA; fused projections.
// R5: 12 warps/CTA (32x32 warp tiles, no spills), MCTA=96, double-buffered
//     H + src staging (one __syncthreads per step).
// ============================================================================

#define NN   20000
#define DEG  16
#define FDIM 128

// ---- p_kernel tiling (proven R2) ----
#define TM       48
#define NTHREADS 384
#define NBLK     ((NN + TM - 1) / TM)     // 417
#define LDW      132
#define SMEM_P   ((size_t)(TM * FDIM + 128 * LDW) * 4)

// ---- lstm mma kernel ----
#define MCTA    96                         // nodes per CTA
#define NCTA2   ((NN + MCTA - 1) / MCTA)   // 209
#define LTH     384                        // 12 warps: 3 rowgroups x 4 colgroups
#define ROWSTR  272                        // fp16 row stride bytes (ldmatrix-safe)
#define HTILE_B (MCTA * ROWSTR)            // 26112
#define WTILE_B (128 * ROWSTR)             // 34816
// SMEM map: src double buffer @0 (2*96*4 -> pad 1024),
//           H0 @1024, H1 @1024+HTILE_B, W slots @SM_W (4 x WTILE_B)
#define SM_H0   1024
#define SM_H1   (SM_H0 + HTILE_B)
#define SM_W    (SM_H1 + HTILE_B)          // 53248
#define SMEM_L  (SM_W + 4 * WTILE_B)       // 192512

__device__ __half g_P16[(size_t)NN * 512];
__device__ float  g_XA [(size_t)NN * FDIM];
__device__ float  g_XB [(size_t)NN * FDIM];

// ---------------------------------------------------------------------------
__device__ __forceinline__ uint32_t smem_u32(const void* p) {
    uint32_t a;
    asm("{ .reg .u64 t; cvta.to.shared.u64 t, %1; cvt.u32.u64 %0, t; }"
        : "=r"(a) : "l"(p));
    return a;
}
__device__ __forceinline__ void ldsm_x4(uint32_t a[4], uint32_t addr) {
    asm volatile("ldmatrix.sync.aligned.m8n8.x4.shared.b16 {%0,%1,%2,%3}, [%4];"
        : "=r"(a[0]), "=r"(a[1]), "=r"(a[2]), "=r"(a[3]) : "r"(addr));
}
__device__ __forceinline__ void ldsm_x2(uint32_t b[2], uint32_t addr) {
    asm volatile("ldmatrix.sync.aligned.m8n8.x2.shared.b16 {%0,%1}, [%2];"
        : "=r"(b[0]), "=r"(b[1]) : "r"(addr));
}
__device__ __forceinline__ void mma16816(float d[4], const uint32_t a[4],
                                         const uint32_t b[2]) {
    asm volatile("mma.sync.aligned.m16n8k16.row.col.f32.f16.f16.f32 "
        "{%0,%1,%2,%3}, {%4,%5,%6,%7}, {%8,%9}, {%0,%1,%2,%3};"
        : "+f"(d[0]), "+f"(d[1]), "+f"(d[2]), "+f"(d[3])
        : "r"(a[0]), "r"(a[1]), "r"(a[2]), "r"(a[3]), "r"(b[0]), "r"(b[1]));
}

// accurate fast transcendentals (~1e-6; NOT tanh.approx)
__device__ __forceinline__ float fsig(float x) {
    float e, r;
    asm("ex2.approx.f32 %0, %1;" : "=f"(e) : "f"(-1.4426950408889634f * x));
    asm("rcp.approx.f32 %0, %1;" : "=f"(r) : "f"(1.0f + e));
    return r;
}
__device__ __forceinline__ float ftanh(float x) {
    return fmaf(2.0f, fsig(2.0f * x), -1.0f);
}

// C[32x32] += A[32x128] * B[32x128]^T for this warp (8 k16 steps, 4 n8 tiles).
__device__ __forceinline__ void mma_tile(uint32_t aAddr, uint32_t bAddr,
                                         float acc[2][4][4]) {
    #pragma unroll
    for (int k0 = 0; k0 < 8; k0++) {
        uint32_t a0[4], a1[4];
        ldsm_x4(a0, aAddr + k0 * 32);
        ldsm_x4(a1, aAddr + 16 * ROWSTR + k0 * 32);
        #pragma unroll
        for (int nt = 0; nt < 4; nt++) {
            uint32_t b[2];
            ldsm_x2(b, bAddr + nt * 8 * ROWSTR + k0 * 32);
            mma16816(acc[0][nt], a0, b);
            mma16816(acc[1][nt], a1, b);
        }
    }
}

// init acc from gathered fp16 P rows (gcol = gate*128 + n0 + q*2)
__device__ __forceinline__ void loadP(float acc[2][4][4],
                                      int r00, int r01, int r10, int r11,
                                      int gcol) {
    const __half* p00 = g_P16 + (size_t)r00 * 512 + gcol;
    const __half* p01 = g_P16 + (size_t)r01 * 512 + gcol;
    const __half* p10 = g_P16 + (size_t)r10 * 512 + gcol;
    const __half* p11 = g_P16 + (size_t)r11 * 512 + gcol;
    #pragma unroll
    for (int nt = 0; nt < 4; nt++) {
        half2 v00 = __ldg((const half2*)(p00 + nt * 8));
        half2 v01 = __ldg((const half2*)(p01 + nt * 8));
        half2 v10 = __ldg((const half2*)(p10 + nt * 8));
        half2 v11 = __ldg((const half2*)(p11 + nt * 8));
        acc[0][nt][0] = __low2float(v00); acc[0][nt][1] = __high2float(v00);
        acc[0][nt][2] = __low2float(v01); acc[0][nt][3] = __high2float(v01);
        acc[1][nt][0] = __low2float(v10); acc[1][nt][1] = __high2float(v10);
        acc[1][nt][2] = __low2float(v11); acc[1][nt][3] = __high2float(v11);
    }
}

// ---------------------------------------------------------------------------
// p_kernel (FFMA, R2-proven), storing fp16
// ---------------------------------------------------------------------------
__device__ __forceinline__ void gemm_48(const float* __restrict__ sA,
                                        const float* __restrict__ sB,
                                        float acc0[8], float acc1[8],
                                        int m0, int tx)
{
    #pragma unroll 4
    for (int k0 = 0; k0 < 128; k0 += 4) {
        const float4 a0 = *(const float4*)(sA + m0 * FDIM + k0);
        const float4 a1 = *(const float4*)(sA + (m0 + 1) * FDIM + k0);
        #pragma unroll
        for (int ig = 0; ig < 8; ig++) {
            const float4 b = *(const float4*)(sB + (ig * 16 + tx) * LDW + k0);
            acc0[ig] = fmaf(a0.x, b.x, acc0[ig]);
            acc0[ig] = fmaf(a0.y, b.y, acc0[ig]);
            acc0[ig] = fmaf(a0.z, b.z, acc0[ig]);
            acc0[ig] = fmaf(a0.w, b.w, acc0[ig]);
            acc1[ig] = fmaf(a1.x, b.x, acc1[ig]);
            acc1[ig] = fmaf(a1.y, b.y, acc1[ig]);
            acc1[ig] = fmaf(a1.z, b.z, acc1[ig]);
            acc1[ig] = fmaf(a1.w, b.w, acc1[ig]);
        }
    }
}

__global__ void __launch_bounds__(NTHREADS)
p_kernel(const float* __restrict__ Xin,
         const float* __restrict__ Wih,
         const float* __restrict__ bih,
         const float* __restrict__ bhh)
{
    extern __shared__ float sm[];
    float* sA = sm;
    float* sB = sm + TM * FDIM;

    const int tid = threadIdx.x;
    const int tx  = tid & 15;
    const int ty  = tid >> 4;
    const int m0  = ty * 2;
    const int n0  = blockIdx.x * TM;
    const int jb  = blockIdx.y * 128;

    for (int idx = tid; idx < TM * 32; idx += NTHREADS) {
        int r = idx >> 5, kq = idx & 31;
        int n = n0 + r; if (n >= NN) n = NN - 1;
        *(float4*)(sA + r * FDIM + kq * 4) =
            *(const float4*)(Xin + (size_t)n * FDIM + kq * 4);
    }
    {
        const float4* gw = (const float4*)(Wih + (size_t)jb * FDIM);
        for (int idx = tid; idx < 128 * 32; idx += NTHREADS) {
            int g = idx >> 5, kq = idx & 31;
            *(float4*)(sB + g * LDW + kq * 4) = gw[idx];
        }
    }
    __syncthreads();

    float acc0[8], acc1[8];
    #pragma unroll
    for (int j = 0; j < 8; j++) {
        int jc = j * 16 + tx;
        float bv = __ldg(bih + jb + jc) + __ldg(bhh + jb + jc);
        acc0[j] = bv; acc1[j] = bv;
    }
    gemm_48(sA, sB, acc0, acc1, m0, tx);

    const int nA = n0 + m0, nB = nA + 1;
    #pragma unroll
    for (int j = 0; j < 8; j++) {
        int jc = j * 16 + tx;
        if (nA < NN) g_P16[(size_t)nA * 512 + jb + jc] = __float2half_rn(acc0[j]);
        if (nB < NN) g_P16[(size_t)nB * 512 + jb + jc] = __float2half_rn(acc1[j]);
    }
}

// ---------------------------------------------------------------------------
// lstm_mma_kernel: CTA = 96 nodes, 12 warps; warp w: rows (w%3)*32..+31,
// gate-cols (w/3)*32..+31. Gate order: i, g, f, o. One sync per step.
// ---------------------------------------------------------------------------
__global__ void __launch_bounds__(LTH, 1)
lstm_mma_kernel(const float* __restrict__ Xin,
                float* __restrict__ Xout,
                const int* __restrict__ src,
                const float* __restrict__ Whh,   // [512,128]
                const float* __restrict__ Wl,    // [outdim,128]
                const float* __restrict__ bl,    // [outdim]
                const float* __restrict__ Wr,    // [outdim,128]
                int outdim, int do_relu, int do_res)
{
    extern __shared__ char smc[];
    const uint32_t sb = smem_u32(smc);
    int* sSrc0 = (int*)(smc);
    int* sSrc1 = (int*)(smc + 512);

    const int tid  = threadIdx.x;
    const int wid  = tid >> 5;
    const int lane = tid & 31;
    const int g8   = lane >> 2;
    const int q    = lane & 3;
    const int m0   = (wid % 3) * 32;      // row group (3 x 32 = 96)
    const int n0   = (wid / 3) * 32;      // col group (4 x 32 = 128)
    const int nblk = blockIdx.x * MCTA;

    // ldmatrix lane addressing
    const uint32_t aLane = (m0 + (lane & 15)) * ROWSTR + ((lane >> 4) * 16);
    const uint32_t aH0   = sb + SM_H0 + aLane;
    const uint32_t aH1   = sb + SM_H1 + aLane;
    const uint32_t bOff  = (n0 + (lane & 7)) * ROWSTR + (((lane >> 3) & 1) * 16);

    // ---- load all 4 Whh gate tiles fp32->fp16; zero H0; stage src[0] -------
    for (int idx = tid; idx < 512 * 64; idx += LTH) {
        int rg = idx >> 6, cp = idx & 63;
        int gate = rg >> 7, row = rg & 127, col = cp * 2;
        float2 v = *(const float2*)(Whh + (size_t)rg * 128 + col);
        *(half2*)(smc + SM_W + gate * WTILE_B + row * ROWSTR + col * 2) =
            __float22half2_rn(v);
    }
    for (int idx = tid; idx < HTILE_B / 16; idx += LTH)
        ((uint4*)(smc + SM_H0))[idx] = make_uint4(0u, 0u, 0u, 0u);
    if (tid < MCTA) {
        int n = nblk + tid;
        sSrc0[tid] = (n < NN) ? __ldg(src + n * DEG) : 0;
    }
    __syncthreads();

    float c[2][4][4];
    #pragma unroll
    for (int mt = 0; mt < 2; mt++)
        #pragma unroll
        for (int nt = 0; nt < 4; nt++)
            #pragma unroll
            for (int e = 0; e < 4; e++) c[mt][nt][e] = 0.0f;

    #pragma unroll 1
    for (int t = 0; t < DEG; t++) {
        const int* sCur   = (t & 1) ? sSrc1 : sSrc0;
        int*       sNext  = (t & 1) ? sSrc0 : sSrc1;
        const uint32_t aH = (t & 1) ? aH1 : aH0;
        char*      hNext  = (t & 1) ? (smc + SM_H0) : (smc + SM_H1);

        const int r00 = sCur[m0 + g8],      r01 = sCur[m0 + g8 + 8];
        const int r10 = sCur[m0 + g8 + 16], r11 = sCur[m0 + g8 + 24];
        const int cq  = n0 + q * 2;

        float acc[2][4][4], tmp[2][4][4];

        // -- gate i: tmp = sig(acc) --
        loadP(acc, r00, r01, r10, r11, 0 * 128 + cq);
        mma_tile(aH, sb + SM_W + 0 * WTILE_B + bOff, acc);
        #pragma unroll
        for (int mt = 0; mt < 2; mt++)
            #pragma unroll
            for (int nt = 0; nt < 4; nt++)
                #pragma unroll
                for (int e = 0; e < 4; e++)
                    tmp[mt][nt][e] = fsig(acc[mt][nt][e]);

        // -- gate g: tmp *= tanh(acc) --
        loadP(acc, r00, r01, r10, r11, 2 * 128 + cq);
        mma_tile(aH, sb + SM_W + 2 * WTILE_B + bOff, acc);
        #pragma unroll
        for (int mt = 0; mt < 2; mt++)
            #pragma unroll
            for (int nt = 0; nt < 4; nt++)
                #pragma unroll
                for (int e = 0; e < 4; e++)
                    tmp[mt][nt][e] *= ftanh(acc[mt][nt][e]);

        // -- gate f: c = sig(acc)*c + tmp --
        loadP(acc, r00, r01, r10, r11, 1 * 128 + cq);
        mma_tile(aH, sb + SM_W + 1 * WTILE_B + bOff, acc);
        #pragma unroll
        for (int mt = 0; mt < 2; mt++)
            #pragma unroll
            for (int nt = 0; nt < 4; nt++)
                #pragma unroll
                for (int e = 0; e < 4; e++)
                    c[mt][nt][e] = fmaf(fsig(acc[mt][nt][e]), c[mt][nt][e],
                                        tmp[mt][nt][e]);

        // -- gate o: raw pre-activation in acc --
        loadP(acc, r00, r01, r10, r11, 3 * 128 + cq);
        mma_tile(aH, sb + SM_W + 3 * WTILE_B + bOff, acc);

        // h = sig(o)*tanh(c) -> OTHER H buffer (no race with readers of aH)
        #pragma unroll
        for (int mt = 0; mt < 2; mt++) {
            const int row = m0 + mt * 16 + g8;
            #pragma unroll
            for (int nt = 0; nt < 4; nt++) {
                const int colb = (n0 + nt * 8 + q * 2) * 2;
                half2 h0 = __floats2half2_rn(
                    fsig(acc[mt][nt][0]) * ftanh(c[mt][nt][0]),
                    fsig(acc[mt][nt][1]) * ftanh(c[mt][nt][1]));
                half2 h1 = __floats2half2_rn(
                    fsig(acc[mt][nt][2]) * ftanh(c[mt][nt][2]),
                    fsig(acc[mt][nt][3]) * ftanh(c[mt][nt][3]));
                *(half2*)(hNext + row * ROWSTR + colb)       = h0;
                *(half2*)(hNext + (row + 8) * ROWSTR + colb) = h1;
            }
        }
        if (tid < MCTA && t + 1 < DEG) {
            int n = nblk + tid;
            sNext[tid] = (n < NN) ? __ldg(src + n * DEG + t + 1) : 0;
        }
        __syncthreads();   // h(t+1), src(t+1) visible; everyone done with aH
    }
    // final H is in buffer (DEG & 1) == 0 -> H0

    // ---- projections: out = H@Wl^T + bl + X@Wr^T (+res)(relu) --------------
    // slot0 <- Wl, slot1 <- Wr (zero-padded rows>=outdim), slot2 <- X fp16
    {
        const half2 z = __float2half2_rn(0.0f);
        for (int idx = tid; idx < 128 * 64; idx += LTH) {
            int row = idx >> 6, cp = idx & 63, col = cp * 2;
            half2 vl = z, vr = z;
            if (row < outdim) {
                vl = __float22half2_rn(*(const float2*)(Wl + (size_t)row * 128 + col));
                vr = __float22half2_rn(*(const float2*)(Wr + (size_t)row * 128 + col));
            }
            int off = row * ROWSTR + col * 2;
            *(half2*)(smc + SM_W + off)           = vl;
            *(half2*)(smc + SM_W + WTILE_B + off) = vr;
            if (row < MCTA) {
                int n = nblk + row; if (n >= NN) n = NN - 1;
                *(half2*)(smc + SM_W + 2 * WTILE_B + off) =
                    __float22half2_rn(*(const float2*)(Xin + (size_t)n * 128 + col));
            }
        }
    }
    __syncthreads();

    float acc[2][4][4];
    #pragma unroll
    for (int mt = 0; mt < 2; mt++) {
        const int row0  = m0 + mt * 16 + g8;
        const int node0 = nblk + row0, node1 = node0 + 8;
        #pragma unroll
        for (int nt = 0; nt < 4; nt++) {
            const int colp = n0 + nt * 8 + q * 2;
            float b0 = 0.f, b1 = 0.f;
            if (colp < outdim) { b0 = __ldg(bl + colp); b1 = __ldg(bl + colp + 1); }
            float x00 = 0.f, x01 = 0.f, x10 = 0.f, x11 = 0.f;
            if (do_res) {
                if (node0 < NN) {
                    float2 v = *(const float2*)(Xin + (size_t)node0 * 128 + colp);
                    x00 = v.x; x01 = v.y;
                }
                if (node1 < NN) {
                    float2 v = *(const float2*)(Xin + (size_t)node1 * 128 + colp);
                    x10 = v.x; x11 = v.y;
                }
            }
            acc[mt][nt][0] = b0 + x00; acc[mt][nt][1] = b1 + x01;
            acc[mt][nt][2] = b0 + x10; acc[mt][nt][3] = b1 + x11;
        }
    }

    const uint32_t aX = sb + SM_W + 2 * WTILE_B + aLane;
    mma_tile(aH0, sb + SM_W + 0 * WTILE_B + bOff, acc);   // H @ Wl^T
    mma_tile(aX,  sb + SM_W + 1 * WTILE_B + bOff, acc);   // X @ Wr^T

    #pragma unroll
    for (int mt = 0; mt < 2; mt++) {
        const int row0  = m0 + mt * 16 + g8;
        const int node0 = nblk + row0, node1 = node0 + 8;
        #pragma unroll
        for (int nt = 0; nt < 4; nt++) {
            const int colp = n0 + nt * 8 + q * 2;
            if (colp >= outdim) continue;
            float v0 = acc[mt][nt][0], v1 = acc[mt][nt][1];
            float v2 = acc[mt][nt][2], v3 = acc[mt][nt][3];
            if (do_relu) {
                v0 = fmaxf(v0, 0.f); v1 = fmaxf(v1, 0.f);
                v2 = fmaxf(v2, 0.f); v3 = fmaxf(v3, 0.f);
            }
            if (node0 < NN)
                *(float2*)(Xout + (size_t)node0 * outdim + colp) = make_float2(v0, v1);
            if (node1 < NN)
                *(float2*)(Xout + (size_t)node1 * outdim + colp) = make_float2(v2, v3);
        }
    }
}

// ---------------------------------------------------------------------------
static void run_layer(const float* Xin, float* Xout, const int* src,
                      const float* Wih, const float* Whh,
                      const float* bih, const float* bhh,
                      const float* Wl, const float* bl, const float* Wr,
                      int outdim, int do_relu, int do_res)
{
    p_kernel<<<dim3(NBLK, 4), NTHREADS, SMEM_P>>>(Xin, Wih, bih, bhh);
    lstm_mma_kernel<<<NCTA2, LTH, SMEM_L>>>(Xin, Xout, src, Whh, Wl, bl, Wr,
                                            outdim, do_relu, do_res);
}

extern "C" void kernel_launch(void* const* d_in, const int* in_sizes, int n_in,
                              void* d_out, int out_size)
{
    (void)in_sizes; (void)n_in; (void)out_size;
    const float* x     = (const float*)d_in[0];
    const int*   src   = (const int*)  d_in[1];
    const float* Wih   = (const float*)d_in[2];   // [4,512,128]
    const float* Whh   = (const float*)d_in[3];   // [4,512,128]
    const float* bih   = (const float*)d_in[4];   // [4,512]
    const float* bhh   = (const float*)d_in[5];   // [4,512]
    const float* Wl123 = (const float*)d_in[6];   // [3,128,128]
    const float* bl123 = (const float*)d_in[7];   // [3,128]
    const float* Wr123 = (const float*)d_in[8];   // [3,128,128]
    const float* Wl4   = (const float*)d_in[9];   // [64,128]
    const float* bl4   = (const float*)d_in[10];  // [64]
    const float* Wr4   = (const float*)d_in[11];  // [64,128]
    float*       out   = (float*)d_out;           // [N,64]

    cudaFuncSetAttribute(p_kernel,
        cudaFuncAttributeMaxDynamicSharedMemorySize, (int)SMEM_P);
    cudaFuncSetAttribute(lstm_mma_kernel,
        cudaFuncAttributeMaxDynamicSharedMemorySize, (int)SMEM_L);

    float *xa = nullptr, *xb = nullptr;
    cudaGetSymbolAddress((void**)&xa, g_XA);
    cudaGetSymbolAddress((void**)&xb, g_XB);

    run_layer(x,  xa, src, Wih + 0 * 512 * 128, Whh + 0 * 512 * 128,
              bih + 0 * 512, bhh + 0 * 512,
              Wl123 + 0 * 128 * 128, bl123 + 0 * 128, Wr123 + 0 * 128 * 128,
              128, 1, 0);
    run_layer(xa, xb, src, Wih + 1 * 512 * 128, Whh + 1 * 512 * 128,
              bih + 1 * 512, bhh + 1 * 512,
              Wl123 + 1 * 128 * 128, bl123 + 1 * 128, Wr123 + 1 * 128 * 128,
              128, 1, 1);
    run_layer(xb, xa, src, Wih + 2 * 512 * 128, Whh + 2 * 512 * 128,
              bih + 2 * 512, bhh + 2 * 512,
              Wl123 + 2 * 128 * 128, bl123 + 2 * 128, Wr123 + 2 * 128 * 128,
              128, 1, 1);
    run_layer(xa, out, src, Wih + 3 * 512 * 128, Whh + 3 * 512 * 128,
              bih + 3 * 512, bhh + 3 * 512,
              Wl4, bl4, Wr4,
              64, 0, 0);
}

// round 7
// speedup vs baseline: 4.9847x; 1.2565x over previous
#include <cuda_runtime.h>
#include <cuda_fp16.h>
#include <cstdint>
#include <cstddef>

// ============================================================================
// ImprovedGraphSAGE via portable mma.sync (HMMA) — sm_100-safe (no tcgen05).
//   p_mma_kernel : P = Xin @ Wih^T + (bih+bhh)  (HMMA, fp16 store)
//   lstm_mma     : 16-step LSTM; H @ Whh^T on HMMA; fused projections.
// R7: fix p_mma accumulator-fragment store (acc[mt] row mapping).
// ============================================================================

#define NN   20000
#define DEG  16
#define FDIM 128

#define MCTA    96                         // nodes per CTA
#define NCTA2   ((NN + MCTA - 1) / MCTA)   // 209
#define LTH     384                        // 12 warps: 3 rowgroups x 4 colgroups
#define ROWSTR  272                        // fp16 row stride bytes (ldmatrix-safe)
#define HTILE_B (MCTA * ROWSTR)            // 26112
#define WTILE_B (128 * ROWSTR)             // 34816

// lstm SMEM map
#define SM_H0   1024
#define SM_H1   (SM_H0 + HTILE_B)
#define SM_W    (SM_H1 + HTILE_B)          // 53248
#define SMEM_L  (SM_W + 4 * WTILE_B)       // 192512

// p_mma SMEM map
#define SM_X    1024
#define SM_PW   (SM_X + HTILE_B)
#define SMEM_PM (SM_PW + 4 * WTILE_B)      // 166400

__device__ __half g_P16[(size_t)NN * 512];
__device__ float  g_XA [(size_t)NN * FDIM];
__device__ float  g_XB [(size_t)NN * FDIM];

// ---------------------------------------------------------------------------
__device__ __forceinline__ uint32_t smem_u32(const void* p) {
    uint32_t a;
    asm("{ .reg .u64 t; cvta.to.shared.u64 t, %1; cvt.u32.u64 %0, t; }"
        : "=r"(a) : "l"(p));
    return a;
}
__device__ __forceinline__ void ldsm_x4(uint32_t a[4], uint32_t addr) {
    asm volatile("ldmatrix.sync.aligned.m8n8.x4.shared.b16 {%0,%1,%2,%3}, [%4];"
        : "=r"(a[0]), "=r"(a[1]), "=r"(a[2]), "=r"(a[3]) : "r"(addr));
}
__device__ __forceinline__ void mma16816(float d[4], const uint32_t a[4],
                                         const uint32_t b[2]) {
    asm volatile("mma.sync.aligned.m16n8k16.row.col.f32.f16.f16.f32 "
        "{%0,%1,%2,%3}, {%4,%5,%6,%7}, {%8,%9}, {%0,%1,%2,%3};"
        : "+f"(d[0]), "+f"(d[1]), "+f"(d[2]), "+f"(d[3])
        : "r"(a[0]), "r"(a[1]), "r"(a[2]), "r"(a[3]), "r"(b[0]), "r"(b[1]));
}

// sigmoid: exact-ish (ex2+rcp, ~1e-6). tanh: MUFU.TANH (rel err ~2^-11,
// same scale as the fp16 h-storage rounding already present).
__device__ __forceinline__ float fsig(float x) {
    float e, r;
    asm("ex2.approx.f32 %0, %1;" : "=f"(e) : "f"(-1.4426950408889634f * x));
    asm("rcp.approx.f32 %0, %1;" : "=f"(r) : "f"(1.0f + e));
    return r;
}
__device__ __forceinline__ float ftanh(float x) {
    float r;
    asm("tanh.approx.f32 %0, %1;" : "=f"(r) : "f"(x));
    return r;
}

// C[32x32] += A[32x128] * B[32x128]^T; B loaded 2 n-tiles per ldmatrix.x4.
__device__ __forceinline__ void mma_tile(uint32_t aAddr, uint32_t bAddr4,
                                         float acc[2][4][4]) {
    #pragma unroll
    for (int k0 = 0; k0 < 8; k0++) {
        uint32_t a0[4], a1[4];
        ldsm_x4(a0, aAddr + k0 * 32);
        ldsm_x4(a1, aAddr + 16 * ROWSTR + k0 * 32);
        #pragma unroll
        for (int np = 0; np < 2; np++) {
            uint32_t b[4];
            ldsm_x4(b, bAddr4 + np * 16 * ROWSTR + k0 * 32);
            mma16816(acc[0][2 * np],     a0, b);
            mma16816(acc[1][2 * np],     a1, b);
            mma16816(acc[0][2 * np + 1], a0, b + 2);
            mma16816(acc[1][2 * np + 1], a1, b + 2);
        }
    }
}

// init acc from gathered fp16 P rows; pB[] hoisted per step, goff = gate*128
__device__ __forceinline__ void loadP(float acc[2][4][4],
                                      const __half* const pB[4], int goff) {
    #pragma unroll
    for (int nt = 0; nt < 4; nt++) {
        half2 v00 = __ldg((const half2*)(pB[0] + goff + nt * 8));
        half2 v01 = __ldg((const half2*)(pB[1] + goff + nt * 8));
        half2 v10 = __ldg((const half2*)(pB[2] + goff + nt * 8));
        half2 v11 = __ldg((const half2*)(pB[3] + goff + nt * 8));
        acc[0][nt][0] = __low2float(v00); acc[0][nt][1] = __high2float(v00);
        acc[0][nt][2] = __low2float(v01); acc[0][nt][3] = __high2float(v01);
        acc[1][nt][0] = __low2float(v10); acc[1][nt][1] = __high2float(v10);
        acc[1][nt][2] = __low2float(v11); acc[1][nt][3] = __high2float(v11);
    }
}

// ---------------------------------------------------------------------------
// p_mma_kernel: P = Xin @ Wih^T + (bih+bhh) on HMMA, fp16 out.
// ---------------------------------------------------------------------------
__global__ void __launch_bounds__(LTH, 1)
p_mma_kernel(const float* __restrict__ Xin,
             const float* __restrict__ Wih,   // [512,128]
             const float* __restrict__ bih,   // [512]
             const float* __restrict__ bhh)   // [512]
{
    extern __shared__ char smc[];
    const uint32_t sb = smem_u32(smc);

    const int tid  = threadIdx.x;
    const int wid  = tid >> 5;
    const int lane = tid & 31;
    const int g8   = lane >> 2;
    const int q    = lane & 3;
    const int m0   = (wid % 3) * 32;
    const int n0   = (wid / 3) * 32;
    const int nblk = blockIdx.x * MCTA;

    // load Wih (4 gate tiles) fp32->fp16
    for (int idx = tid; idx < 512 * 64; idx += LTH) {
        int rg = idx >> 6, cp = idx & 63;
        int gate = rg >> 7, row = rg & 127, col = cp * 2;
        float2 v = *(const float2*)(Wih + (size_t)rg * 128 + col);
        *(half2*)(smc + SM_PW + gate * WTILE_B + row * ROWSTR + col * 2) =
            __float22half2_rn(v);
    }
    // load X tile fp32->fp16 (clamp OOB rows)
    for (int idx = tid; idx < MCTA * 64; idx += LTH) {
        int row = idx >> 6, cp = idx & 63, col = cp * 2;
        int n = nblk + row; if (n >= NN) n = NN - 1;
        float2 v = *(const float2*)(Xin + (size_t)n * FDIM + col);
        *(half2*)(smc + SM_X + row * ROWSTR + col * 2) = __float22half2_rn(v);
    }
    __syncthreads();

    const uint32_t aX    = sb + SM_X + (m0 + (lane & 15)) * ROWSTR + ((lane >> 4) * 16);
    const uint32_t bOff4 = (n0 + (lane & 7) + ((lane >> 4) << 3)) * ROWSTR +
                           (((lane >> 3) & 1) * 16);

    #pragma unroll 1
    for (int g = 0; g < 4; g++) {
        float acc[2][4][4];
        #pragma unroll
        for (int nt = 0; nt < 4; nt++) {
            int col = g * 128 + n0 + nt * 8 + q * 2;
            float b0 = __ldg(bih + col)     + __ldg(bhh + col);
            float b1 = __ldg(bih + col + 1) + __ldg(bhh + col + 1);
            acc[0][nt][0] = b0; acc[0][nt][1] = b1;
            acc[0][nt][2] = b0; acc[0][nt][3] = b1;
            acc[1][nt][0] = b0; acc[1][nt][1] = b1;
            acc[1][nt][2] = b0; acc[1][nt][3] = b1;
        }
        mma_tile(aX, sb + SM_PW + g * WTILE_B + bOff4, acc);

        // FIXED: d[0..1] -> row m0+mt*16+g8, d[2..3] -> row m0+mt*16+g8+8
        #pragma unroll
        for (int mt = 0; mt < 2; mt++) {
            const int node0 = nblk + m0 + mt * 16 + g8;
            const int node1 = node0 + 8;
            #pragma unroll
            for (int nt = 0; nt < 4; nt++) {
                const int col = g * 128 + n0 + nt * 8 + q * 2;
                if (node0 < NN)
                    *(half2*)(g_P16 + (size_t)node0 * 512 + col) =
                        __floats2half2_rn(acc[mt][nt][0], acc[mt][nt][1]);
                if (node1 < NN)
                    *(half2*)(g_P16 + (size_t)node1 * 512 + col) =
                        __floats2half2_rn(acc[mt][nt][2], acc[mt][nt][3]);
            }
        }
    }
}

// ---------------------------------------------------------------------------
// lstm_mma_kernel: CTA = 96 nodes, 12 warps; gate order i, g, f, o.
// ---------------------------------------------------------------------------
__global__ void __launch_bounds__(LTH, 1)
lstm_mma_kernel(const float* __restrict__ Xin,
                float* __restrict__ Xout,
                const int* __restrict__ src,
                const float* __restrict__ Whh,   // [512,128]
                const float* __restrict__ Wl,    // [outdim,128]
                const float* __restrict__ bl,    // [outdim]
                const float* __restrict__ Wr,    // [outdim,128]
                int outdim, int do_relu, int do_res)
{
    extern __shared__ char smc[];
    const uint32_t sb = smem_u32(smc);
    int* sSrc0 = (int*)(smc);
    int* sSrc1 = (int*)(smc + 512);

    const int tid  = threadIdx.x;
    const int wid  = tid >> 5;
    const int lane = tid & 31;
    const int g8   = lane >> 2;
    const int q    = lane & 3;
    const int m0   = (wid % 3) * 32;
    const int n0   = (wid / 3) * 32;
    const int nblk = blockIdx.x * MCTA;

    const uint32_t aLane = (m0 + (lane & 15)) * ROWSTR + ((lane >> 4) * 16);
    const uint32_t aH0   = sb + SM_H0 + aLane;
    const uint32_t aH1   = sb + SM_H1 + aLane;
    const uint32_t bOff4 = (n0 + (lane & 7) + ((lane >> 4) << 3)) * ROWSTR +
                           (((lane >> 3) & 1) * 16);

    for (int idx = tid; idx < 512 * 64; idx += LTH) {
        int rg = idx >> 6, cp = idx & 63;
        int gate = rg >> 7, row = rg & 127, col = cp * 2;
        float2 v = *(const float2*)(Whh + (size_t)rg * 128 + col);
        *(half2*)(smc + SM_W + gate * WTILE_B + row * ROWSTR + col * 2) =
            __float22half2_rn(v);
    }
    for (int idx = tid; idx < HTILE_B / 16; idx += LTH)
        ((uint4*)(smc + SM_H0))[idx] = make_uint4(0u, 0u, 0u, 0u);
    if (tid < MCTA) {
        int n = nblk + tid;
        sSrc0[tid] = (n < NN) ? __ldg(src + n * DEG) : 0;
    }
    __syncthreads();

    float c[2][4][4];
    #pragma unroll
    for (int mt = 0; mt < 2; mt++)
        #pragma unroll
        for (int nt = 0; nt < 4; nt++)
            #pragma unroll
            for (int e = 0; e < 4; e++) c[mt][nt][e] = 0.0f;

    #pragma unroll 1
    for (int t = 0; t < DEG; t++) {
        const int* sCur   = (t & 1) ? sSrc1 : sSrc0;
        int*       sNext  = (t & 1) ? sSrc0 : sSrc1;
        const uint32_t aH = (t & 1) ? aH1 : aH0;
        char*      hNext  = (t & 1) ? (smc + SM_H0) : (smc + SM_H1);

        const int cq = n0 + q * 2;
        const __half* pB[4];
        pB[0] = g_P16 + (size_t)sCur[m0 + g8]      * 512 + cq;
        pB[1] = g_P16 + (size_t)sCur[m0 + g8 + 8]  * 512 + cq;
        pB[2] = g_P16 + (size_t)sCur[m0 + g8 + 16] * 512 + cq;
        pB[3] = g_P16 + (size_t)sCur[m0 + g8 + 24] * 512 + cq;

        float acc[2][4][4], tmp[2][4][4];

        // -- gate i: tmp = sig(acc) --
        loadP(acc, pB, 0 * 128);
        mma_tile(aH, sb + SM_W + 0 * WTILE_B + bOff4, acc);
        #pragma unroll
        for (int mt = 0; mt < 2; mt++)
            #pragma unroll
            for (int nt = 0; nt < 4; nt++)
                #pragma unroll
                for (int e = 0; e < 4; e++)
                    tmp[mt][nt][e] = fsig(acc[mt][nt][e]);

        // -- gate g: tmp *= tanh(acc) --
        loadP(acc, pB, 2 * 128);
        mma_tile(aH, sb + SM_W + 2 * WTILE_B + bOff4, acc);
        #pragma unroll
        for (int mt = 0; mt < 2; mt++)
            #pragma unroll
            for (int nt = 0; nt < 4; nt++)
                #pragma unroll
                for (int e = 0; e < 4; e++)
                    tmp[mt][nt][e] *= ftanh(acc[mt][nt][e]);

        // -- gate f: c = sig(acc)*c + tmp --
        loadP(acc, pB, 1 * 128);
        mma_tile(aH, sb + SM_W + 1 * WTILE_B + bOff4, acc);
        #pragma unroll
        for (int mt = 0; mt < 2; mt++)
            #pragma unroll
            for (int nt = 0; nt < 4; nt++)
                #pragma unroll
                for (int e = 0; e < 4; e++)
                    c[mt][nt][e] = fmaf(fsig(acc[mt][nt][e]), c[mt][nt][e],
                                        tmp[mt][nt][e]);

        // -- gate o: raw pre-activation in acc --
        loadP(acc, pB, 3 * 128);
        mma_tile(aH, sb + SM_W + 3 * WTILE_B + bOff4, acc);

        // h = sig(o)*tanh(c) -> other H buffer
        #pragma unroll
        for (int mt = 0; mt < 2; mt++) {
            const int row = m0 + mt * 16 + g8;
            #pragma unroll
            for (int nt = 0; nt < 4; nt++) {
                const int colb = (n0 + nt * 8 + q * 2) * 2;
                half2 h0 = __floats2half2_rn(
                    fsig(acc[mt][nt][0]) * ftanh(c[mt][nt][0]),
                    fsig(acc[mt][nt][1]) * ftanh(c[mt][nt][1]));
                half2 h1 = __floats2half2_rn(
                    fsig(acc[mt][nt][2]) * ftanh(c[mt][nt][2]),
                    fsig(acc[mt][nt][3]) * ftanh(c[mt][nt][3]));
                *(half2*)(hNext + row * ROWSTR + colb)       = h0;
                *(half2*)(hNext + (row + 8) * ROWSTR + colb) = h1;
            }
        }
        if (tid < MCTA && t + 1 < DEG) {
            int n = nblk + tid;
            sNext[tid] = (n < NN) ? __ldg(src + n * DEG + t + 1) : 0;
        }
        __syncthreads();
    }
    // final H in buffer H0 (DEG even)

    // ---- projections: out = H@Wl^T + bl + X@Wr^T (+res)(relu) --------------
    {
        const half2 z = __float2half2_rn(0.0f);
        for (int idx = tid; idx < 128 * 64; idx += LTH) {
            int row = idx >> 6, cp = idx & 63, col = cp * 2;
            half2 vl = z, vr = z;
            if (row < outdim) {
                vl = __float22half2_rn(*(const float2*)(Wl + (size_t)row * 128 + col));
                vr = __float22half2_rn(*(const float2*)(Wr + (size_t)row * 128 + col));
            }
            int off = row * ROWSTR + col * 2;
            *(half2*)(smc + SM_W + off)           = vl;
            *(half2*)(smc + SM_W + WTILE_B + off) = vr;
            if (row < MCTA) {
                int n = nblk + row; if (n >= NN) n = NN - 1;
                *(half2*)(smc + SM_W + 2 * WTILE_B + off) =
                    __float22half2_rn(*(const float2*)(Xin + (size_t)n * 128 + col));
            }
        }
    }
    __syncthreads();

    float acc[2][4][4];
    #pragma unroll
    for (int mt = 0; mt < 2; mt++) {
        const int row0  = m0 + mt * 16 + g8;
        const int node0 = nblk + row0, node1 = node0 + 8;
        #pragma unroll
        for (int nt = 0; nt < 4; nt++) {
            const int colp = n0 + nt * 8 + q * 2;
            float b0 = 0.f, b1 = 0.f;
            if (colp < outdim) { b0 = __ldg(bl + colp); b1 = __ldg(bl + colp + 1); }
            float x00 = 0.f, x01 = 0.f, x10 = 0.f, x11 = 0.f;
            if (do_res) {
                if (node0 < NN) {
                    float2 v = *(const float2*)(Xin + (size_t)node0 * 128 + colp);
                    x00 = v.x; x01 = v.y;
                }
                if (node1 < NN) {
                    float2 v = *(const float2*)(Xin + (size_t)node1 * 128 + colp);
                    x10 = v.x; x11 = v.y;
                }
            }
            acc[mt][nt][0] = b0 + x00; acc[mt][nt][1] = b1 + x01;
            acc[mt][nt][2] = b0 + x10; acc[mt][nt][3] = b1 + x11;
        }
    }

    const uint32_t aX = sb + SM_W + 2 * WTILE_B + aLane;
    mma_tile(aH0, sb + SM_W + 0 * WTILE_B + bOff4, acc);   // H @ Wl^T
    mma_tile(aX,  sb + SM_W + 1 * WTILE_B + bOff4, acc);   // X @ Wr^T

    #pragma unroll
    for (int mt = 0; mt < 2; mt++) {
        const int row0  = m0 + mt * 16 + g8;
        const int node0 = nblk + row0, node1 = node0 + 8;
        #pragma unroll
        for (int nt = 0; nt < 4; nt++) {
            const int colp = n0 + nt * 8 + q * 2;
            if (colp >= outdim) continue;
            float v0 = acc[mt][nt][0], v1 = acc[mt][nt][1];
            float v2 = acc[mt][nt][2], v3 = acc[mt][nt][3];
            if (do_relu) {
                v0 = fmaxf(v0, 0.f); v1 = fmaxf(v1, 0.f);
                v2 = fmaxf(v2, 0.f); v3 = fmaxf(v3, 0.f);
            }
            if (node0 < NN)
                *(float2*)(Xout + (size_t)node0 * outdim + colp) = make_float2(v0, v1);
            if (node1 < NN)
                *(float2*)(Xout + (size_t)node1 * outdim + colp) = make_float2(v2, v3);
        }
    }
}

// ---------------------------------------------------------------------------
static void run_layer(const float* Xin, float* Xout, const int* src,
                      const float* Wih, const float* Whh,
                      const float* bih, const float* bhh,
                      const float* Wl, const float* bl, const float* Wr,
                      int outdim, int do_relu, int do_res)
{
    p_mma_kernel<<<NCTA2, LTH, SMEM_PM>>>(Xin, Wih, bih, bhh);
    lstm_mma_kernel<<<NCTA2, LTH, SMEM_L>>>(Xin, Xout, src, Whh, Wl, bl, Wr,
                                            outdim, do_relu, do_res);
}

extern "C" void kernel_launch(void* const* d_in, const int* in_sizes, int n_in,
                              void* d_out, int out_size)
{
    (void)in_sizes; (void)n_in; (void)out_size;
    const float* x     = (const float*)d_in[0];
    const int*   src   = (const int*)  d_in[1];
    const float* Wih   = (const float*)d_in[2];   // [4,512,128]
    const float* Whh   = (const float*)d_in[3];   // [4,512,128]
    const float* bih   = (const float*)d_in[4];   // [4,512]
    const float* bhh   = (const float*)d_in[5];   // [4,512]
    const float* Wl123 = (const float*)d_in[6];   // [3,128,128]
    const float* bl123 = (const float*)d_in[7];   // [3,128]
    const float* Wr123 = (const float*)d_in[8];   // [3,128,128]
    const float* Wl4   = (const float*)d_in[9];   // [64,128]
    const float* bl4   = (const float*)d_in[10];  // [64]
    const float* Wr4   = (const float*)d_in[11];  // [64,128]
    float*       out   = (float*)d_out;           // [N,64]

    cudaFuncSetAttribute(p_mma_kernel,
        cudaFuncAttributeMaxDynamicSharedMemorySize, (int)SMEM_PM);
    cudaFuncSetAttribute(lstm_mma_kernel,
        cudaFuncAttributeMaxDynamicSharedMemorySize, (int)SMEM_L);

    float *xa = nullptr, *xb = nullptr;
    cudaGetSymbolAddress((void**)&xa, g_XA);
    cudaGetSymbolAddress((void**)&xb, g_XB);

    run_layer(x,  xa, src, Wih + 0 * 512 * 128, Whh + 0 * 512 * 128,
              bih + 0 * 512, bhh + 0 * 512,
              Wl123 + 0 * 128 * 128, bl123 + 0 * 128, Wr123 + 0 * 128 * 128,
              128, 1, 0);
    run_layer(xa, xb, src, Wih + 1 * 512 * 128, Whh + 1 * 512 * 128,
              bih + 1 * 512, bhh + 1 * 512,
              Wl123 + 1 * 128 * 128, bl123 + 1 * 128, Wr123 + 1 * 128 * 128,
              128, 1, 1);
    run_layer(xb, xa, src, Wih + 2 * 512 * 128, Whh + 2 * 512 * 128,
              bih + 2 * 512, bhh + 2 * 512,
              Wl123 + 2 * 128 * 128, bl123 + 2 * 128, Wr123 + 2 * 128 * 128,
              128, 1, 1);
    run_layer(xa, out, src, Wih + 3 * 512 * 128, Whh + 3 * 512 * 128,
              bih + 3 * 512, bhh + 3 * 512,
              Wl4, bl4, Wr4,
              64, 0, 0);
}

// round 8
// speedup vs baseline: 5.7958x; 1.1627x over previous
#include <cuda_runtime.h>
#include <cuda_fp16.h>
#include <cstdint>
#include <cstddef>

// ============================================================================
// ImprovedGraphSAGE via portable mma.sync (HMMA) — sm_100-safe (no tcgen05).
//   p_mma_kernel : P = Xin @ Wih^T + (bih+bhh)  (HMMA, fp16 store)
//                  gates i,f,o PRE-SCALED by 0.5 (sigmoid-via-tanh trick)
//   lstm_mma     : 16-step LSTM; H @ Whh^T on HMMA; fused projections.
// R8: sigmoid(z) = 0.5*tanh(z/2)+0.5 with z/2 produced directly by the MMA
//     (weights/biases of gates i,f,o scaled by 0.5) -> 1 MUFU per sigmoid.
// ============================================================================

#define NN   20000
#define DEG  16
#define FDIM 128

#define MCTA    96                         // nodes per CTA
#define NCTA2   ((NN + MCTA - 1) / MCTA)   // 209
#define LTH     384                        // 12 warps: 3 rowgroups x 4 colgroups
#define ROWSTR  272                        // fp16 row stride bytes (ldmatrix-safe)
#define HTILE_B (MCTA * ROWSTR)            // 26112
#define WTILE_B (128 * ROWSTR)             // 34816

// lstm SMEM map
#define SM_H0   1024
#define SM_H1   (SM_H0 + HTILE_B)
#define SM_W    (SM_H1 + HTILE_B)          // 53248
#define SMEM_L  (SM_W + 4 * WTILE_B)       // 192512

// p_mma SMEM map
#define SM_X    1024
#define SM_PW   (SM_X + HTILE_B)
#define SMEM_PM (SM_PW + 4 * WTILE_B)      // 166400

__device__ __half g_P16[(size_t)NN * 512];
__device__ float  g_XA [(size_t)NN * FDIM];
__device__ float  g_XB [(size_t)NN * FDIM];

// ---------------------------------------------------------------------------
__device__ __forceinline__ uint32_t smem_u32(const void* p) {
    uint32_t a;
    asm("{ .reg .u64 t; cvta.to.shared.u64 t, %1; cvt.u32.u64 %0, t; }"
        : "=r"(a) : "l"(p));
    return a;
}
__device__ __forceinline__ void ldsm_x4(uint32_t a[4], uint32_t addr) {
    asm volatile("ldmatrix.sync.aligned.m8n8.x4.shared.b16 {%0,%1,%2,%3}, [%4];"
        : "=r"(a[0]), "=r"(a[1]), "=r"(a[2]), "=r"(a[3]) : "r"(addr));
}
__device__ __forceinline__ void mma16816(float d[4], const uint32_t a[4],
                                         const uint32_t b[2]) {
    asm volatile("mma.sync.aligned.m16n8k16.row.col.f32.f16.f16.f32 "
        "{%0,%1,%2,%3}, {%4,%5,%6,%7}, {%8,%9}, {%0,%1,%2,%3};"
        : "+f"(d[0]), "+f"(d[1]), "+f"(d[2]), "+f"(d[3])
        : "r"(a[0]), "r"(a[1]), "r"(a[2]), "r"(a[3]), "r"(b[0]), "r"(b[1]));
}

// tanh: MUFU.TANH (rel err ~2^-11). Sigmoid of the ORIGINAL pre-activation z
// is fmaf(0.5, ftanh(z/2), 0.5) where z/2 comes out of the MMA directly
// (gates i,f,o have weights+biases pre-scaled by 0.5).
__device__ __forceinline__ float ftanh(float x) {
    float r;
    asm("tanh.approx.f32 %0, %1;" : "=f"(r) : "f"(x));
    return r;
}
__device__ __forceinline__ float fsig_pre(float half_z) {   // takes z/2
    return fmaf(0.5f, ftanh(half_z), 0.5f);
}

// C[32x32] += A[32x128] * B[32x128]^T; B loaded 2 n-tiles per ldmatrix.x4.
__device__ __forceinline__ void mma_tile(uint32_t aAddr, uint32_t bAddr4,
                                         float acc[2][4][4]) {
    #pragma unroll
    for (int k0 = 0; k0 < 8; k0++) {
        uint32_t a0[4], a1[4];
        ldsm_x4(a0, aAddr + k0 * 32);
        ldsm_x4(a1, aAddr + 16 * ROWSTR + k0 * 32);
        #pragma unroll
        for (int np = 0; np < 2; np++) {
            uint32_t b[4];
            ldsm_x4(b, bAddr4 + np * 16 * ROWSTR + k0 * 32);
            mma16816(acc[0][2 * np],     a0, b);
            mma16816(acc[1][2 * np],     a1, b);
            mma16816(acc[0][2 * np + 1], a0, b + 2);
            mma16816(acc[1][2 * np + 1], a1, b + 2);
        }
    }
}

// init acc from gathered fp16 P rows; pB[] hoisted per step, goff = gate*128
__device__ __forceinline__ void loadP(float acc[2][4][4],
                                      const __half* const pB[4], int goff) {
    #pragma unroll
    for (int nt = 0; nt < 4; nt++) {
        half2 v00 = __ldg((const half2*)(pB[0] + goff + nt * 8));
        half2 v01 = __ldg((const half2*)(pB[1] + goff + nt * 8));
        half2 v10 = __ldg((const half2*)(pB[2] + goff + nt * 8));
        half2 v11 = __ldg((const half2*)(pB[3] + goff + nt * 8));
        acc[0][nt][0] = __low2float(v00); acc[0][nt][1] = __high2float(v00);
        acc[0][nt][2] = __low2float(v01); acc[0][nt][3] = __high2float(v01);
        acc[1][nt][0] = __low2float(v10); acc[1][nt][1] = __high2float(v10);
        acc[1][nt][2] = __low2float(v11); acc[1][nt][3] = __high2float(v11);
    }
}

// gate scale: 0.5 for i(0), f(1), o(3); 1.0 for g(2)
__device__ __forceinline__ float gate_scale(int gate) {
    return (gate == 2) ? 1.0f : 0.5f;
}

// ---------------------------------------------------------------------------
// p_mma_kernel: P = scale_g * (Xin @ Wih^T + (bih+bhh)) on HMMA, fp16 out.
// ---------------------------------------------------------------------------
__global__ void __launch_bounds__(LTH, 1)
p_mma_kernel(const float* __restrict__ Xin,
             const float* __restrict__ Wih,   // [512,128]
             const float* __restrict__ bih,   // [512]
             const float* __restrict__ bhh)   // [512]
{
    extern __shared__ char smc[];
    const uint32_t sb = smem_u32(smc);

    const int tid  = threadIdx.x;
    const int wid  = tid >> 5;
    const int lane = tid & 31;
    const int g8   = lane >> 2;
    const int q    = lane & 3;
    const int m0   = (wid % 3) * 32;
    const int n0   = (wid / 3) * 32;
    const int nblk = blockIdx.x * MCTA;

    // load Wih (4 gate tiles) fp32->fp16, pre-scaled per gate
    for (int idx = tid; idx < 512 * 64; idx += LTH) {
        int rg = idx >> 6, cp = idx & 63;
        int gate = rg >> 7, row = rg & 127, col = cp * 2;
        float sc = gate_scale(gate);
        float2 v = *(const float2*)(Wih + (size_t)rg * 128 + col);
        v.x *= sc; v.y *= sc;
        *(half2*)(smc + SM_PW + gate * WTILE_B + row * ROWSTR + col * 2) =
            __float22half2_rn(v);
    }
    // load X tile fp32->fp16 (clamp OOB rows)
    for (int idx = tid; idx < MCTA * 64; idx += LTH) {
        int row = idx >> 6, cp = idx & 63, col = cp * 2;
        int n = nblk + row; if (n >= NN) n = NN - 1;
        float2 v = *(const float2*)(Xin + (size_t)n * FDIM + col);
        *(half2*)(smc + SM_X + row * ROWSTR + col * 2) = __float22half2_rn(v);
    }
    __syncthreads();

    const uint32_t aX    = sb + SM_X + (m0 + (lane & 15)) * ROWSTR + ((lane >> 4) * 16);
    const uint32_t bOff4 = (n0 + (lane & 7) + ((lane >> 4) << 3)) * ROWSTR +
                           (((lane >> 3) & 1) * 16);

    #pragma unroll 1
    for (int g = 0; g < 4; g++) {
        const float sc = gate_scale(g);
        float acc[2][4][4];
        #pragma unroll
        for (int nt = 0; nt < 4; nt++) {
            int col = g * 128 + n0 + nt * 8 + q * 2;
            float b0 = sc * (__ldg(bih + col)     + __ldg(bhh + col));
            float b1 = sc * (__ldg(bih + col + 1) + __ldg(bhh + col + 1));
            acc[0][nt][0] = b0; acc[0][nt][1] = b1;
            acc[0][nt][2] = b0; acc[0][nt][3] = b1;
            acc[1][nt][0] = b0; acc[1][nt][1] = b1;
            acc[1][nt][2] = b0; acc[1][nt][3] = b1;
        }
        mma_tile(aX, sb + SM_PW + g * WTILE_B + bOff4, acc);

        // d[0..1] -> row m0+mt*16+g8, d[2..3] -> row m0+mt*16+g8+8
        #pragma unroll
        for (int mt = 0; mt < 2; mt++) {
            const int node0 = nblk + m0 + mt * 16 + g8;
            const int node1 = node0 + 8;
            #pragma unroll
            for (int nt = 0; nt < 4; nt++) {
                const int col = g * 128 + n0 + nt * 8 + q * 2;
                if (node0 < NN)
                    *(half2*)(g_P16 + (size_t)node0 * 512 + col) =
                        __floats2half2_rn(acc[mt][nt][0], acc[mt][nt][1]);
                if (node1 < NN)
                    *(half2*)(g_P16 + (size_t)node1 * 512 + col) =
                        __floats2half2_rn(acc[mt][nt][2], acc[mt][nt][3]);
            }
        }
    }
}

// ---------------------------------------------------------------------------
// lstm_mma_kernel: CTA = 96 nodes, 12 warps; gate order i, g, f, o.
// Gates i,f,o arrive as z/2 (pre-scaled weights); sigmoid = fsig_pre.
// ---------------------------------------------------------------------------
__global__ void __launch_bounds__(LTH, 1)
lstm_mma_kernel(const float* __restrict__ Xin,
                float* __restrict__ Xout,
                const int* __restrict__ src,
                const float* __restrict__ Whh,   // [512,128]
                const float* __restrict__ Wl,    // [outdim,128]
                const float* __restrict__ bl,    // [outdim]
                const float* __restrict__ Wr,    // [outdim,128]
                int outdim, int do_relu, int do_res)
{
    extern __shared__ char smc[];
    const uint32_t sb = smem_u32(smc);
    int* sSrc0 = (int*)(smc);
    int* sSrc1 = (int*)(smc + 512);

    const int tid  = threadIdx.x;
    const int wid  = tid >> 5;
    const int lane = tid & 31;
    const int g8   = lane >> 2;
    const int q    = lane & 3;
    const int m0   = (wid % 3) * 32;
    const int n0   = (wid / 3) * 32;
    const int nblk = blockIdx.x * MCTA;

    const uint32_t aLane = (m0 + (lane & 15)) * ROWSTR + ((lane >> 4) * 16);
    const uint32_t aH0   = sb + SM_H0 + aLane;
    const uint32_t aH1   = sb + SM_H1 + aLane;
    const uint32_t bOff4 = (n0 + (lane & 7) + ((lane >> 4) << 3)) * ROWSTR +
                           (((lane >> 3) & 1) * 16);

    // Whh fp32->fp16, pre-scaled per gate
    for (int idx = tid; idx < 512 * 64; idx += LTH) {
        int rg = idx >> 6, cp = idx & 63;
        int gate = rg >> 7, row = rg & 127, col = cp * 2;
        float sc = gate_scale(gate);
        float2 v = *(const float2*)(Whh + (size_t)rg * 128 + col);
        v.x *= sc; v.y *= sc;
        *(half2*)(smc + SM_W + gate * WTILE_B + row * ROWSTR + col * 2) =
            __float22half2_rn(v);
    }
    for (int idx = tid; idx < HTILE_B / 16; idx += LTH)
        ((uint4*)(smc + SM_H0))[idx] = make_uint4(0u, 0u, 0u, 0u);
    if (tid < MCTA) {
        int n = nblk + tid;
        sSrc0[tid] = (n < NN) ? __ldg(src + n * DEG) : 0;
    }
    __syncthreads();

    float c[2][4][4];
    #pragma unroll
    for (int mt = 0; mt < 2; mt++)
        #pragma unroll
        for (int nt = 0; nt < 4; nt++)
            #pragma unroll
            for (int e = 0; e < 4; e++) c[mt][nt][e] = 0.0f;

    #pragma unroll 1
    for (int t = 0; t < DEG; t++) {
        const int* sCur   = (t & 1) ? sSrc1 : sSrc0;
        int*       sNext  = (t & 1) ? sSrc0 : sSrc1;
        const uint32_t aH = (t & 1) ? aH1 : aH0;
        char*      hNext  = (t & 1) ? (smc + SM_H0) : (smc + SM_H1);

        const int cq = n0 + q * 2;
        const __half* pB[4];
        pB[0] = g_P16 + (size_t)sCur[m0 + g8]      * 512 + cq;
        pB[1] = g_P16 + (size_t)sCur[m0 + g8 + 8]  * 512 + cq;
        pB[2] = g_P16 + (size_t)sCur[m0 + g8 + 16] * 512 + cq;
        pB[3] = g_P16 + (size_t)sCur[m0 + g8 + 24] * 512 + cq;

        float acc[2][4][4], tmp[2][4][4];

        // -- gate i (z/2): tmp = sigmoid --
        loadP(acc, pB, 0 * 128);
        mma_tile(aH, sb + SM_W + 0 * WTILE_B + bOff4, acc);
        #pragma unroll
        for (int mt = 0; mt < 2; mt++)
            #pragma unroll
            for (int nt = 0; nt < 4; nt++)
                #pragma unroll
                for (int e = 0; e < 4; e++)
                    tmp[mt][nt][e] = fsig_pre(acc[mt][nt][e]);

        // -- gate g (unscaled): tmp *= tanh(acc) --
        loadP(acc, pB, 2 * 128);
        mma_tile(aH, sb + SM_W + 2 * WTILE_B + bOff4, acc);
        #pragma unroll
        for (int mt = 0; mt < 2; mt++)
            #pragma unroll
            for (int nt = 0; nt < 4; nt++)
                #pragma unroll
                for (int e = 0; e < 4; e++)
                    tmp[mt][nt][e] *= ftanh(acc[mt][nt][e]);

        // -- gate f (z/2): c = sigmoid*c + tmp --
        loadP(acc, pB, 1 * 128);
        mma_tile(aH, sb + SM_W + 1 * WTILE_B + bOff4, acc);
        #pragma unroll
        for (int mt = 0; mt < 2; mt++)
            #pragma unroll
            for (int nt = 0; nt < 4; nt++)
                #pragma unroll
                for (int e = 0; e < 4; e++)
                    c[mt][nt][e] = fmaf(fsig_pre(acc[mt][nt][e]), c[mt][nt][e],
                                        tmp[mt][nt][e]);

        // -- gate o (z/2): raw half-pre-activation stays in acc --
        loadP(acc, pB, 3 * 128);
        mma_tile(aH, sb + SM_W + 3 * WTILE_B + bOff4, acc);

        // h = sigmoid(o)*tanh(c) -> other H buffer
        #pragma unroll
        for (int mt = 0; mt < 2; mt++) {
            const int row = m0 + mt * 16 + g8;
            #pragma unroll
            for (int nt = 0; nt < 4; nt++) {
                const int colb = (n0 + nt * 8 + q * 2) * 2;
                half2 h0 = __floats2half2_rn(
                    fsig_pre(acc[mt][nt][0]) * ftanh(c[mt][nt][0]),
                    fsig_pre(acc[mt][nt][1]) * ftanh(c[mt][nt][1]));
                half2 h1 = __floats2half2_rn(
                    fsig_pre(acc[mt][nt][2]) * ftanh(c[mt][nt][2]),
                    fsig_pre(acc[mt][nt][3]) * ftanh(c[mt][nt][3]));
                *(half2*)(hNext + row * ROWSTR + colb)       = h0;
                *(half2*)(hNext + (row + 8) * ROWSTR + colb) = h1;
            }
        }
        if (tid < MCTA && t + 1 < DEG) {
            int n = nblk + tid;
            sNext[tid] = (n < NN) ? __ldg(src + n * DEG + t + 1) : 0;
        }
        __syncthreads();
    }
    // final H in buffer H0 (DEG even)

    // ---- projections: out = H@Wl^T + bl + X@Wr^T (+res)(relu) --------------
    {
        const half2 z = __float2half2_rn(0.0f);
        for (int idx = tid; idx < 128 * 64; idx += LTH) {
            int row = idx >> 6, cp = idx & 63, col = cp * 2;
            half2 vl = z, vr = z;
            if (row < outdim) {
                vl = __float22half2_rn(*(const float2*)(Wl + (size_t)row * 128 + col));
                vr = __float22half2_rn(*(const float2*)(Wr + (size_t)row * 128 + col));
            }
            int off = row * ROWSTR + col * 2;
            *(half2*)(smc + SM_W + off)           = vl;
            *(half2*)(smc + SM_W + WTILE_B + off) = vr;
            if (row < MCTA) {
                int n = nblk + row; if (n >= NN) n = NN - 1;
                *(half2*)(smc + SM_W + 2 * WTILE_B + off) =
                    __float22half2_rn(*(const float2*)(Xin + (size_t)n * 128 + col));
            }
        }
    }
    __syncthreads();

    float acc[2][4][4];
    #pragma unroll
    for (int mt = 0; mt < 2; mt++) {
        const int row0  = m0 + mt * 16 + g8;
        const int node0 = nblk + row0, node1 = node0 + 8;
        #pragma unroll
        for (int nt = 0; nt < 4; nt++) {
            const int colp = n0 + nt * 8 + q * 2;
            float b0 = 0.f, b1 = 0.f;
            if (colp < outdim) { b0 = __ldg(bl + colp); b1 = __ldg(bl + colp + 1); }
            float x00 = 0.f, x01 = 0.f, x10 = 0.f, x11 = 0.f;
            if (do_res) {
                if (node0 < NN) {
                    float2 v = *(const float2*)(Xin + (size_t)node0 * 128 + colp);
                    x00 = v.x; x01 = v.y;
                }
                if (node1 < NN) {
                    float2 v = *(const float2*)(Xin + (size_t)node1 * 128 + colp);
                    x10 = v.x; x11 = v.y;
                }
            }
            acc[mt][nt][0] = b0 + x00; acc[mt][nt][1] = b1 + x01;
            acc[mt][nt][2] = b0 + x10; acc[mt][nt][3] = b1 + x11;
        }
    }

    const uint32_t aX = sb + SM_W + 2 * WTILE_B + aLane;
    mma_tile(aH0, sb + SM_W + 0 * WTILE_B + bOff4, acc);   // H @ Wl^T
    mma_tile(aX,  sb + SM_W + 1 * WTILE_B + bOff4, acc);   // X @ Wr^T

    #pragma unroll
    for (int mt = 0; mt < 2; mt++) {
        const int row0  = m0 + mt * 16 + g8;
        const int node0 = nblk + row0, node1 = node0 + 8;
        #pragma unroll
        for (int nt = 0; nt < 4; nt++) {
            const int colp = n0 + nt * 8 + q * 2;
            if (colp >= outdim) continue;
            float v0 = acc[mt][nt][0], v1 = acc[mt][nt][1];
            float v2 = acc[mt][nt][2], v3 = acc[mt][nt][3];
            if (do_relu) {
                v0 = fmaxf(v0, 0.f); v1 = fmaxf(v1, 0.f);
                v2 = fmaxf(v2, 0.f); v3 = fmaxf(v3, 0.f);
            }
            if (node0 < NN)
                *(float2*)(Xout + (size_t)node0 * outdim + colp) = make_float2(v0, v1);
            if (node1 < NN)
                *(float2*)(Xout + (size_t)node1 * outdim + colp) = make_float2(v2, v3);
        }
    }
}

// ---------------------------------------------------------------------------
static void run_layer(const float* Xin, float* Xout, const int* src,
                      const float* Wih, const float* Whh,
                      const float* bih, const float* bhh,
                      const float* Wl, const float* bl, const float* Wr,
                      int outdim, int do_relu, int do_res)
{
    p_mma_kernel<<<NCTA2, LTH, SMEM_PM>>>(Xin, Wih, bih, bhh);
    lstm_mma_kernel<<<NCTA2, LTH, SMEM_L>>>(Xin, Xout, src, Whh, Wl, bl, Wr,
                                            outdim, do_relu, do_res);
}

extern "C" void kernel_launch(void* const* d_in, const int* in_sizes, int n_in,
                              void* d_out, int out_size)
{
    (void)in_sizes; (void)n_in; (void)out_size;
    const float* x     = (const float*)d_in[0];
    const int*   src   = (const int*)  d_in[1];
    const float* Wih   = (const float*)d_in[2];   // [4,512,128]
    const float* Whh   = (const float*)d_in[3];   // [4,512,128]
    const float* bih   = (const float*)d_in[4];   // [4,512]
    const float* bhh   = (const float*)d_in[5];   // [4,512]
    const float* Wl123 = (const float*)d_in[6];   // [3,128,128]
    const float* bl123 = (const float*)d_in[7];   // [3,128]
    const float* Wr123 = (const float*)d_in[8];   // [3,128,128]
    const float* Wl4   = (const float*)d_in[9];   // [64,128]
    const float* bl4   = (const float*)d_in[10];  // [64]
    const float* Wr4   = (const float*)d_in[11];  // [64,128]
    float*       out   = (float*)d_out;           // [N,64]

    cudaFuncSetAttribute(p_mma_kernel,
        cudaFuncAttributeMaxDynamicSharedMemorySize, (int)SMEM_PM);
    cudaFuncSetAttribute(lstm_mma_kernel,
        cudaFuncAttributeMaxDynamicSharedMemorySize, (int)SMEM_L);

    float *xa = nullptr, *xb = nullptr;
    cudaGetSymbolAddress((void**)&xa, g_XA);
    cudaGetSymbolAddress((void**)&xb, g_XB);

    run_layer(x,  xa, src, Wih + 0 * 512 * 128, Whh + 0 * 512 * 128,
              bih + 0 * 512, bhh + 0 * 512,
              Wl123 + 0 * 128 * 128, bl123 + 0 * 128, Wr123 + 0 * 128 * 128,
              128, 1, 0);
    run_layer(xa, xb, src, Wih + 1 * 512 * 128, Whh + 1 * 512 * 128,
              bih + 1 * 512, bhh + 1 * 512,
              Wl123 + 1 * 128 * 128, bl123 + 1 * 128, Wr123 + 1 * 128 * 128,
              128, 1, 1);
    run_layer(xb, xa, src, Wih + 2 * 512 * 128, Whh + 2 * 512 * 128,
              bih + 2 * 512, bhh + 2 * 512,
              Wl123 + 2 * 128 * 128, bl123 + 2 * 128, Wr123 + 2 * 128 * 128,
              128, 1, 1);
    run_layer(xa, out, src, Wih + 3 * 512 * 128, Whh + 3 * 512 * 128,
              bih + 3 * 512, bhh + 3 * 512,
              Wl4, bl4, Wr4,
              64, 0, 0);
}

// round 9
// speedup vs baseline: 6.2476x; 1.0779x over previous
#include <cuda_runtime.h>
#include <cuda_fp16.h>
#include <cstdint>
#include <cstddef>

// ============================================================================
// ImprovedGraphSAGE via portable mma.sync (HMMA) — sm_100-safe (no tcgen05).
//   p_mma_kernel : P = Xin @ Wih^T + (bih+bhh)  (HMMA, fp16 store)
//                  gates i,f,o PRE-SCALED by 0.5 (sigmoid-via-tanh trick)
//   lstm_mma     : 16-step LSTM; H @ Whh^T on HMMA; fused projections.
// R9: MCTA 96->48 (16x32 warp tiles) — grid 417 for 3-wave makespan 1.5 vs
//     2.0 "units"; fixes the 2-wave quantization tail of grid=209.
// ============================================================================

#define NN   20000
#define DEG  16
#define FDIM 128

#define MCTA    48                         // nodes per CTA
#define NCTA2   ((NN + MCTA - 1) / MCTA)   // 417
#define LTH     384                        // 12 warps: 3 rowgroups x 4 colgroups
#define ROWSTR  272                        // fp16 row stride bytes (ldmatrix-safe)
#define HTILE_B (MCTA * ROWSTR)            // 13056
#define WTILE_B (128 * ROWSTR)             // 34816

// lstm SMEM map
#define SM_H0   1024
#define SM_H1   (SM_H0 + HTILE_B)
#define SM_W    (SM_H1 + HTILE_B)          // 27136
#define SMEM_L  (SM_W + 4 * WTILE_B)       // 166400

// p_mma SMEM map
#define SM_X    1024
#define SM_PW   (SM_X + HTILE_B)
#define SMEM_PM (SM_PW + 4 * WTILE_B)      // 153344

__device__ __half g_P16[(size_t)NN * 512];
__device__ float  g_XA [(size_t)NN * FDIM];
__device__ float  g_XB [(size_t)NN * FDIM];

// ---------------------------------------------------------------------------
__device__ __forceinline__ uint32_t smem_u32(const void* p) {
    uint32_t a;
    asm("{ .reg .u64 t; cvta.to.shared.u64 t, %1; cvt.u32.u64 %0, t; }"
        : "=r"(a) : "l"(p));
    return a;
}
__device__ __forceinline__ void ldsm_x4(uint32_t a[4], uint32_t addr) {
    asm volatile("ldmatrix.sync.aligned.m8n8.x4.shared.b16 {%0,%1,%2,%3}, [%4];"
        : "=r"(a[0]), "=r"(a[1]), "=r"(a[2]), "=r"(a[3]) : "r"(addr));
}
__device__ __forceinline__ void mma16816(float d[4], const uint32_t a[4],
                                         const uint32_t b[2]) {
    asm volatile("mma.sync.aligned.m16n8k16.row.col.f32.f16.f16.f32 "
        "{%0,%1,%2,%3}, {%4,%5,%6,%7}, {%8,%9}, {%0,%1,%2,%3};"
        : "+f"(d[0]), "+f"(d[1]), "+f"(d[2]), "+f"(d[3])
        : "r"(a[0]), "r"(a[1]), "r"(a[2]), "r"(a[3]), "r"(b[0]), "r"(b[1]));
}

// tanh: MUFU.TANH. Sigmoid of original z = fmaf(0.5, tanh(z/2), 0.5), where
// z/2 comes out of the MMA directly (gates i,f,o pre-scaled by 0.5).
__device__ __forceinline__ float ftanh(float x) {
    float r;
    asm("tanh.approx.f32 %0, %1;" : "=f"(r) : "f"(x));
    return r;
}
__device__ __forceinline__ float fsig_pre(float half_z) {
    return fmaf(0.5f, ftanh(half_z), 0.5f);
}

// C[16x32] += A[16x128] * B[32x128]^T (8 k16 steps, 2 B-ldsm.x4 per k).
__device__ __forceinline__ void mma_tile16(uint32_t aAddr, uint32_t bAddr4,
                                           float acc[4][4]) {
    #pragma unroll
    for (int k0 = 0; k0 < 8; k0++) {
        uint32_t a[4];
        ldsm_x4(a, aAddr + k0 * 32);
        #pragma unroll
        for (int np = 0; np < 2; np++) {
            uint32_t b[4];
            ldsm_x4(b, bAddr4 + np * 16 * ROWSTR + k0 * 32);
            mma16816(acc[2 * np],     a, b);
            mma16816(acc[2 * np + 1], a, b + 2);
        }
    }
}

// init acc from the 2 gathered fp16 P rows of this thread (rows g8, g8+8)
__device__ __forceinline__ void loadP(float acc[4][4],
                                      const __half* p0, const __half* p1,
                                      int goff) {
    #pragma unroll
    for (int nt = 0; nt < 4; nt++) {
        half2 v0 = __ldg((const half2*)(p0 + goff + nt * 8));
        half2 v1 = __ldg((const half2*)(p1 + goff + nt * 8));
        acc[nt][0] = __low2float(v0); acc[nt][1] = __high2float(v0);
        acc[nt][2] = __low2float(v1); acc[nt][3] = __high2float(v1);
    }
}

// gate scale: 0.5 for i(0), f(1), o(3); 1.0 for g(2)
__device__ __forceinline__ float gate_scale(int gate) {
    return (gate == 2) ? 1.0f : 0.5f;
}

// ---------------------------------------------------------------------------
// p_mma_kernel: P = scale_g * (Xin @ Wih^T + (bih+bhh)) on HMMA, fp16 out.
// ---------------------------------------------------------------------------
__global__ void __launch_bounds__(LTH, 1)
p_mma_kernel(const float* __restrict__ Xin,
             const float* __restrict__ Wih,   // [512,128]
             const float* __restrict__ bih,   // [512]
             const float* __restrict__ bhh)   // [512]
{
    extern __shared__ char smc[];
    const uint32_t sb = smem_u32(smc);

    const int tid  = threadIdx.x;
    const int wid  = tid >> 5;
    const int lane = tid & 31;
    const int g8   = lane >> 2;
    const int q    = lane & 3;
    const int m0   = (wid % 3) * 16;
    const int n0   = (wid / 3) * 32;
    const int nblk = blockIdx.x * MCTA;

    // load Wih (4 gate tiles) fp32->fp16, pre-scaled per gate
    for (int idx = tid; idx < 512 * 64; idx += LTH) {
        int rg = idx >> 6, cp = idx & 63;
        int gate = rg >> 7, row = rg & 127, col = cp * 2;
        float sc = gate_scale(gate);
        float2 v = *(const float2*)(Wih + (size_t)rg * 128 + col);
        v.x *= sc; v.y *= sc;
        *(half2*)(smc + SM_PW + gate * WTILE_B + row * ROWSTR + col * 2) =
            __float22half2_rn(v);
    }
    // load X tile fp32->fp16 (clamp OOB rows)
    for (int idx = tid; idx < MCTA * 64; idx += LTH) {
        int row = idx >> 6, cp = idx & 63, col = cp * 2;
        int n = nblk + row; if (n >= NN) n = NN - 1;
        float2 v = *(const float2*)(Xin + (size_t)n * FDIM + col);
        *(half2*)(smc + SM_X + row * ROWSTR + col * 2) = __float22half2_rn(v);
    }
    __syncthreads();

    const uint32_t aX    = sb + SM_X + (m0 + (lane & 15)) * ROWSTR + ((lane >> 4) * 16);
    const uint32_t bOff4 = (n0 + (lane & 7) + ((lane >> 4) << 3)) * ROWSTR +
                           (((lane >> 3) & 1) * 16);

    #pragma unroll 1
    for (int g = 0; g < 4; g++) {
        const float sc = gate_scale(g);
        float acc[4][4];
        #pragma unroll
        for (int nt = 0; nt < 4; nt++) {
            int col = g * 128 + n0 + nt * 8 + q * 2;
            float b0 = sc * (__ldg(bih + col)     + __ldg(bhh + col));
            float b1 = sc * (__ldg(bih + col + 1) + __ldg(bhh + col + 1));
            acc[nt][0] = b0; acc[nt][1] = b1;
            acc[nt][2] = b0; acc[nt][3] = b1;
        }
        mma_tile16(aX, sb + SM_PW + g * WTILE_B + bOff4, acc);

        // d[0..1] -> row m0+g8, d[2..3] -> row m0+g8+8
        const int node0 = nblk + m0 + g8;
        const int node1 = node0 + 8;
        #pragma unroll
        for (int nt = 0; nt < 4; nt++) {
            const int col = g * 128 + n0 + nt * 8 + q * 2;
            if (node0 < NN)
                *(half2*)(g_P16 + (size_t)node0 * 512 + col) =
                    __floats2half2_rn(acc[nt][0], acc[nt][1]);
            if (node1 < NN)
                *(half2*)(g_P16 + (size_t)node1 * 512 + col) =
                    __floats2half2_rn(acc[nt][2], acc[nt][3]);
        }
    }
}

// ---------------------------------------------------------------------------
// lstm_mma_kernel: CTA = 48 nodes, 12 warps (16x32 tiles); gates i, g, f, o.
// ---------------------------------------------------------------------------
__global__ void __launch_bounds__(LTH, 1)
lstm_mma_kernel(const float* __restrict__ Xin,
                float* __restrict__ Xout,
                const int* __restrict__ src,
                const float* __restrict__ Whh,   // [512,128]
                const float* __restrict__ Wl,    // [outdim,128]
                const float* __restrict__ bl,    // [outdim]
                const float* __restrict__ Wr,    // [outdim,128]
                int outdim, int do_relu, int do_res)
{
    extern __shared__ char smc[];
    const uint32_t sb = smem_u32(smc);
    int* sSrc0 = (int*)(smc);
    int* sSrc1 = (int*)(smc + 512);

    const int tid  = threadIdx.x;
    const int wid  = tid >> 5;
    const int lane = tid & 31;
    const int g8   = lane >> 2;
    const int q    = lane & 3;
    const int m0   = (wid % 3) * 16;
    const int n0   = (wid / 3) * 32;
    const int nblk = blockIdx.x * MCTA;

    const uint32_t aLane = (m0 + (lane & 15)) * ROWSTR + ((lane >> 4) * 16);
    const uint32_t aH0   = sb + SM_H0 + aLane;
    const uint32_t aH1   = sb + SM_H1 + aLane;
    const uint32_t bOff4 = (n0 + (lane & 7) + ((lane >> 4) << 3)) * ROWSTR +
                           (((lane >> 3) & 1) * 16);

    // Whh fp32->fp16, pre-scaled per gate
    for (int idx = tid; idx < 512 * 64; idx += LTH) {
        int rg = idx >> 6, cp = idx & 63;
        int gate = rg >> 7, row = rg & 127, col = cp * 2;
        float sc = gate_scale(gate);
        float2 v = *(const float2*)(Whh + (size_t)rg * 128 + col);
        v.x *= sc; v.y *= sc;
        *(half2*)(smc + SM_W + gate * WTILE_B + row * ROWSTR + col * 2) =
            __float22half2_rn(v);
    }
    for (int idx = tid; idx < HTILE_B / 16; idx += LTH)
        ((uint4*)(smc + SM_H0))[idx] = make_uint4(0u, 0u, 0u, 0u);
    if (tid < MCTA) {
        int n = nblk + tid;
        sSrc0[tid] = (n < NN) ? __ldg(src + n * DEG) : 0;
    }
    __syncthreads();

    float c[4][4];
    #pragma unroll
    for (int nt = 0; nt < 4; nt++)
        #pragma unroll
        for (int e = 0; e < 4; e++) c[nt][e] = 0.0f;

    #pragma unroll 1
    for (int t = 0; t < DEG; t++) {
        const int* sCur   = (t & 1) ? sSrc1 : sSrc0;
        int*       sNext  = (t & 1) ? sSrc0 : sSrc1;
        const uint32_t aH = (t & 1) ? aH1 : aH0;
        char*      hNext  = (t & 1) ? (smc + SM_H0) : (smc + SM_H1);

        const int cq = n0 + q * 2;
        const __half* p0 = g_P16 + (size_t)sCur[m0 + g8]     * 512 + cq;
        const __half* p1 = g_P16 + (size_t)sCur[m0 + g8 + 8] * 512 + cq;

        float acc[4][4], tmp[4][4];

        // -- gate i (z/2): tmp = sigmoid --
        loadP(acc, p0, p1, 0 * 128);
        mma_tile16(aH, sb + SM_W + 0 * WTILE_B + bOff4, acc);
        #pragma unroll
        for (int nt = 0; nt < 4; nt++)
            #pragma unroll
            for (int e = 0; e < 4; e++)
                tmp[nt][e] = fsig_pre(acc[nt][e]);

        // -- gate g (unscaled): tmp *= tanh(acc) --
        loadP(acc, p0, p1, 2 * 128);
        mma_tile16(aH, sb + SM_W + 2 * WTILE_B + bOff4, acc);
        #pragma unroll
        for (int nt = 0; nt < 4; nt++)
            #pragma unroll
            for (int e = 0; e < 4; e++)
                tmp[nt][e] *= ftanh(acc[nt][e]);

        // -- gate f (z/2): c = sigmoid*c + tmp --
        loadP(acc, p0, p1, 1 * 128);
        mma_tile16(aH, sb + SM_W + 1 * WTILE_B + bOff4, acc);
        #pragma unroll
        for (int nt = 0; nt < 4; nt++)
            #pragma unroll
            for (int e = 0; e < 4; e++)
                c[nt][e] = fmaf(fsig_pre(acc[nt][e]), c[nt][e], tmp[nt][e]);

        // -- gate o (z/2): raw half-pre-activation stays in acc --
        loadP(acc, p0, p1, 3 * 128);
        mma_tile16(aH, sb + SM_W + 3 * WTILE_B + bOff4, acc);

        // h = sigmoid(o)*tanh(c) -> other H buffer
        {
            const int row = m0 + g8;
            #pragma unroll
            for (int nt = 0; nt < 4; nt++) {
                const int colb = (n0 + nt * 8 + q * 2) * 2;
                half2 h0 = __floats2half2_rn(
                    fsig_pre(acc[nt][0]) * ftanh(c[nt][0]),
                    fsig_pre(acc[nt][1]) * ftanh(c[nt][1]));
                half2 h1 = __floats2half2_rn(
                    fsig_pre(acc[nt][2]) * ftanh(c[nt][2]),
                    fsig_pre(acc[nt][3]) * ftanh(c[nt][3]));
                *(half2*)(hNext + row * ROWSTR + colb)       = h0;
                *(half2*)(hNext + (row + 8) * ROWSTR + colb) = h1;
            }
        }
        if (tid < MCTA && t + 1 < DEG) {
            int n = nblk + tid;
            sNext[tid] = (n < NN) ? __ldg(src + n * DEG + t + 1) : 0;
        }
        __syncthreads();
    }
    // final H in buffer H0 (DEG even)

    // ---- projections: out = H@Wl^T + bl + X@Wr^T (+res)(relu) --------------
    {
        const half2 z = __float2half2_rn(0.0f);
        for (int idx = tid; idx < 128 * 64; idx += LTH) {
            int row = idx >> 6, cp = idx & 63, col = cp * 2;
            half2 vl = z, vr = z;
            if (row < outdim) {
                vl = __float22half2_rn(*(const float2*)(Wl + (size_t)row * 128 + col));
                vr = __float22half2_rn(*(const float2*)(Wr + (size_t)row * 128 + col));
            }
            int off = row * ROWSTR + col * 2;
            *(half2*)(smc + SM_W + off)           = vl;
            *(half2*)(smc + SM_W + WTILE_B + off) = vr;
            if (row < MCTA) {
                int n = nblk + row; if (n >= NN) n = NN - 1;
                *(half2*)(smc + SM_W + 2 * WTILE_B + off) =
                    __float22half2_rn(*(const float2*)(Xin + (size_t)n * 128 + col));
            }
        }
    }
    __syncthreads();

    float acc[4][4];
    {
        const int node0 = nblk + m0 + g8, node1 = node0 + 8;
        #pragma unroll
        for (int nt = 0; nt < 4; nt++) {
            const int colp = n0 + nt * 8 + q * 2;
            float b0 = 0.f, b1 = 0.f;
            if (colp < outdim) { b0 = __ldg(bl + colp); b1 = __ldg(bl + colp + 1); }
            float x00 = 0.f, x01 = 0.f, x10 = 0.f, x11 = 0.f;
            if (do_res) {
                if (node0 < NN) {
                    float2 v = *(const float2*)(Xin + (size_t)node0 * 128 + colp);
                    x00 = v.x; x01 = v.y;
                }
                if (node1 < NN) {
                    float2 v = *(const float2*)(Xin + (size_t)node1 * 128 + colp);
                    x10 = v.x; x11 = v.y;
                }
            }
            acc[nt][0] = b0 + x00; acc[nt][1] = b1 + x01;
            acc[nt][2] = b0 + x10; acc[nt][3] = b1 + x11;
        }
    }

    const uint32_t aX = sb + SM_W + 2 * WTILE_B + aLane;
    mma_tile16(aH0, sb + SM_W + 0 * WTILE_B + bOff4, acc);   // H @ Wl^T
    mma_tile16(aX,  sb + SM_W + 1 * WTILE_B + bOff4, acc);   // X @ Wr^T

    {
        const int node0 = nblk + m0 + g8, node1 = node0 + 8;
        #pragma unroll
        for (int nt = 0; nt < 4; nt++) {
            const int colp = n0 + nt * 8 + q * 2;
            if (colp >= outdim) continue;
            float v0 = acc[nt][0], v1 = acc[nt][1];
            float v2 = acc[nt][2], v3 = acc[nt][3];
            if (do_relu) {
                v0 = fmaxf(v0, 0.f); v1 = fmaxf(v1, 0.f);
                v2 = fmaxf(v2, 0.f); v3 = fmaxf(v3, 0.f);
            }
            if (node0 < NN)
                *(float2*)(Xout + (size_t)node0 * outdim + colp) = make_float2(v0, v1);
            if (node1 < NN)
                *(float2*)(Xout + (size_t)node1 * outdim + colp) = make_float2(v2, v3);
        }
    }
}

// ---------------------------------------------------------------------------
static void run_layer(const float* Xin, float* Xout, const int* src,
                      const float* Wih, const float* Whh,
                      const float* bih, const float* bhh,
                      const float* Wl, const float* bl, const float* Wr,
                      int outdim, int do_relu, int do_res)
{
    p_mma_kernel<<<NCTA2, LTH, SMEM_PM>>>(Xin, Wih, bih, bhh);
    lstm_mma_kernel<<<NCTA2, LTH, SMEM_L>>>(Xin, Xout, src, Whh, Wl, bl, Wr,
                                            outdim, do_relu, do_res);
}

extern "C" void kernel_launch(void* const* d_in, const int* in_sizes, int n_in,
                              void* d_out, int out_size)
{
    (void)in_sizes; (void)n_in; (void)out_size;
    const float* x     = (const float*)d_in[0];
    const int*   src   = (const int*)  d_in[1];
    const float* Wih   = (const float*)d_in[2];   // [4,512,128]
    const float* Whh   = (const float*)d_in[3];   // [4,512,128]
    const float* bih   = (const float*)d_in[4];   // [4,512]
    const float* bhh   = (const float*)d_in[5];   // [4,512]
    const float* Wl123 = (const float*)d_in[6];   // [3,128,128]
    const float* bl123 = (const float*)d_in[7];   // [3,128]
    const float* Wr123 = (const float*)d_in[8];   // [3,128,128]
    const float* Wl4   = (const float*)d_in[9];   // [64,128]
    const float* bl4   = (const float*)d_in[10];  // [64]
    const float* Wr4   = (const float*)d_in[11];  // [64,128]
    float*       out   = (float*)d_out;           // [N,64]

    cudaFuncSetAttribute(p_mma_kernel,
        cudaFuncAttributeMaxDynamicSharedMemorySize, (int)SMEM_PM);
    cudaFuncSetAttribute(lstm_mma_kernel,
        cudaFuncAttributeMaxDynamicSharedMemorySize, (int)SMEM_L);

    float *xa = nullptr, *xb = nullptr;
    cudaGetSymbolAddress((void**)&xa, g_XA);
    cudaGetSymbolAddress((void**)&xb, g_XB);

    run_layer(x,  xa, src, Wih + 0 * 512 * 128, Whh + 0 * 512 * 128,
              bih + 0 * 512, bhh + 0 * 512,
              Wl123 + 0 * 128 * 128, bl123 + 0 * 128, Wr123 + 0 * 128 * 128,
              128, 1, 0);
    run_layer(xa, xb, src, Wih + 1 * 512 * 128, Whh + 1 * 512 * 128,
              bih + 1 * 512, bhh + 1 * 512,
              Wl123 + 1 * 128 * 128, bl123 + 1 * 128, Wr123 + 1 * 128 * 128,
              128, 1, 1);
    run_layer(xb, xa, src, Wih + 2 * 512 * 128, Whh + 2 * 512 * 128,
              bih + 2 * 512, bhh + 2 * 512,
              Wl123 + 2 * 128 * 128, bl123 + 2 * 128, Wr123 + 2 * 128 * 128,
              128, 1, 1);
    run_layer(xa, out, src, Wih + 3 * 512 * 128, Whh + 3 * 512 * 128,
              bih + 3 * 512, bhh + 3 * 512,
              Wl4, bl4, Wr4,
              64, 0, 0);
}

// round 10
// speedup vs baseline: 6.2683x; 1.0033x over previous
#include <cuda_runtime.h>
#include <cuda_fp16.h>
#include <cstdint>
#include <cstddef>

// ============================================================================
// ImprovedGraphSAGE via portable mma.sync (HMMA) — sm_100-safe (no tcgen05).
//   p_mma_kernel : P = Xin @ Wih^T + (bih+bhh)  (HMMA, fp16 store)
//                  gates i,f,o PRE-SCALED by 0.5 (sigmoid-via-tanh trick)
//   lstm_mma     : 16-step LSTM; H @ Whh^T on HMMA; fused projections.
// R10: A-fragment register caching across the 4 gate GEMMs (-25% ldsm
//      traffic on an L1-bound kernel). MCTA=48 retained for the 3-wave
//      makespan win.
// ============================================================================

#define NN   20000
#define DEG  16
#define FDIM 128

#define MCTA    48                         // nodes per CTA
#define NCTA2   ((NN + MCTA - 1) / MCTA)   // 417
#define LTH     384                        // 12 warps: 3 rowgroups x 4 colgroups
#define ROWSTR  272                        // fp16 row stride bytes (ldmatrix-safe)
#define HTILE_B (MCTA * ROWSTR)            // 13056
#define WTILE_B (128 * ROWSTR)             // 34816

// lstm SMEM map
#define SM_H0   1024
#define SM_H1   (SM_H0 + HTILE_B)
#define SM_W    (SM_H1 + HTILE_B)          // 27136
#define SMEM_L  (SM_W + 4 * WTILE_B)       // 166400

// p_mma SMEM map
#define SM_X    1024
#define SM_PW   (SM_X + HTILE_B)
#define SMEM_PM (SM_PW + 4 * WTILE_B)      // 153344

__device__ __half g_P16[(size_t)NN * 512];
__device__ float  g_XA [(size_t)NN * FDIM];
__device__ float  g_XB [(size_t)NN * FDIM];

// ---------------------------------------------------------------------------
__device__ __forceinline__ uint32_t smem_u32(const void* p) {
    uint32_t a;
    asm("{ .reg .u64 t; cvta.to.shared.u64 t, %1; cvt.u32.u64 %0, t; }"
        : "=r"(a) : "l"(p));
    return a;
}
__device__ __forceinline__ void ldsm_x4(uint32_t a[4], uint32_t addr) {
    asm volatile("ldmatrix.sync.aligned.m8n8.x4.shared.b16 {%0,%1,%2,%3}, [%4];"
        : "=r"(a[0]), "=r"(a[1]), "=r"(a[2]), "=r"(a[3]) : "r"(addr));
}
__device__ __forceinline__ void mma16816(float d[4], const uint32_t a[4],
                                         const uint32_t b[2]) {
    asm volatile("mma.sync.aligned.m16n8k16.row.col.f32.f16.f16.f32 "
        "{%0,%1,%2,%3}, {%4,%5,%6,%7}, {%8,%9}, {%0,%1,%2,%3};"
        : "+f"(d[0]), "+f"(d[1]), "+f"(d[2]), "+f"(d[3])
        : "r"(a[0]), "r"(a[1]), "r"(a[2]), "r"(a[3]), "r"(b[0]), "r"(b[1]));
}

// tanh: MUFU.TANH. Sigmoid of original z = fmaf(0.5, tanh(z/2), 0.5), where
// z/2 comes out of the MMA directly (gates i,f,o pre-scaled by 0.5).
__device__ __forceinline__ float ftanh(float x) {
    float r;
    asm("tanh.approx.f32 %0, %1;" : "=f"(r) : "f"(x));
    return r;
}
__device__ __forceinline__ float fsig_pre(float half_z) {
    return fmaf(0.5f, ftanh(half_z), 0.5f);
}

// Load the warp's 16x128 A-operand fragments once (8 k16 chains).
__device__ __forceinline__ void lda_frags(uint32_t aF[8][4], uint32_t aAddr) {
    #pragma unroll
    for (int k0 = 0; k0 < 8; k0++)
        ldsm_x4(aF[k0], aAddr + k0 * 32);
}

// C[16x32] += A(cached) * B[32x128]^T (8 k16 steps, 2 B-ldsm.x4 per k).
__device__ __forceinline__ void mma_tile16A(const uint32_t aF[8][4],
                                            uint32_t bAddr4, float acc[4][4]) {
    #pragma unroll
    for (int k0 = 0; k0 < 8; k0++) {
        #pragma unroll
        for (int np = 0; np < 2; np++) {
            uint32_t b[4];
            ldsm_x4(b, bAddr4 + np * 16 * ROWSTR + k0 * 32);
            mma16816(acc[2 * np],     aF[k0], b);
            mma16816(acc[2 * np + 1], aF[k0], b + 2);
        }
    }
}

// init acc from the 2 gathered fp16 P rows of this thread (rows g8, g8+8)
__device__ __forceinline__ void loadP(float acc[4][4],
                                      const __half* p0, const __half* p1,
                                      int goff) {
    #pragma unroll
    for (int nt = 0; nt < 4; nt++) {
        half2 v0 = __ldg((const half2*)(p0 + goff + nt * 8));
        half2 v1 = __ldg((const half2*)(p1 + goff + nt * 8));
        acc[nt][0] = __low2float(v0); acc[nt][1] = __high2float(v0);
        acc[nt][2] = __low2float(v1); acc[nt][3] = __high2float(v1);
    }
}

// gate scale: 0.5 for i(0), f(1), o(3); 1.0 for g(2)
__device__ __forceinline__ float gate_scale(int gate) {
    return (gate == 2) ? 1.0f : 0.5f;
}

// ---------------------------------------------------------------------------
// p_mma_kernel: P = scale_g * (Xin @ Wih^T + (bih+bhh)) on HMMA, fp16 out.
// ---------------------------------------------------------------------------
__global__ void __launch_bounds__(LTH, 1)
p_mma_kernel(const float* __restrict__ Xin,
             const float* __restrict__ Wih,   // [512,128]
             const float* __restrict__ bih,   // [512]
             const float* __restrict__ bhh)   // [512]
{
    extern __shared__ char smc[];
    const uint32_t sb = smem_u32(smc);

    const int tid  = threadIdx.x;
    const int wid  = tid >> 5;
    const int lane = tid & 31;
    const int g8   = lane >> 2;
    const int q    = lane & 3;
    const int m0   = (wid % 3) * 16;
    const int n0   = (wid / 3) * 32;
    const int nblk = blockIdx.x * MCTA;

    // load Wih (4 gate tiles) fp32->fp16, pre-scaled per gate
    for (int idx = tid; idx < 512 * 64; idx += LTH) {
        int rg = idx >> 6, cp = idx & 63;
        int gate = rg >> 7, row = rg & 127, col = cp * 2;
        float sc = gate_scale(gate);
        float2 v = *(const float2*)(Wih + (size_t)rg * 128 + col);
        v.x *= sc; v.y *= sc;
        *(half2*)(smc + SM_PW + gate * WTILE_B + row * ROWSTR + col * 2) =
            __float22half2_rn(v);
    }
    // load X tile fp32->fp16 (clamp OOB rows)
    for (int idx = tid; idx < MCTA * 64; idx += LTH) {
        int row = idx >> 6, cp = idx & 63, col = cp * 2;
        int n = nblk + row; if (n >= NN) n = NN - 1;
        float2 v = *(const float2*)(Xin + (size_t)n * FDIM + col);
        *(half2*)(smc + SM_X + row * ROWSTR + col * 2) = __float22half2_rn(v);
    }
    __syncthreads();

    const uint32_t aX    = sb + SM_X + (m0 + (lane & 15)) * ROWSTR + ((lane >> 4) * 16);
    const uint32_t bOff4 = (n0 + (lane & 7) + ((lane >> 4) << 3)) * ROWSTR +
                           (((lane >> 3) & 1) * 16);

    uint32_t aF[8][4];
    lda_frags(aF, aX);   // X fragments reused across all 4 gates

    #pragma unroll 1
    for (int g = 0; g < 4; g++) {
        const float sc = gate_scale(g);
        float acc[4][4];
        #pragma unroll
        for (int nt = 0; nt < 4; nt++) {
            int col = g * 128 + n0 + nt * 8 + q * 2;
            float b0 = sc * (__ldg(bih + col)     + __ldg(bhh + col));
            float b1 = sc * (__ldg(bih + col + 1) + __ldg(bhh + col + 1));
            acc[nt][0] = b0; acc[nt][1] = b1;
            acc[nt][2] = b0; acc[nt][3] = b1;
        }
        mma_tile16A(aF, sb + SM_PW + g * WTILE_B + bOff4, acc);

        // d[0..1] -> row m0+g8, d[2..3] -> row m0+g8+8
        const int node0 = nblk + m0 + g8;
        const int node1 = node0 + 8;
        #pragma unroll
        for (int nt = 0; nt < 4; nt++) {
            const int col = g * 128 + n0 + nt * 8 + q * 2;
            if (node0 < NN)
                *(half2*)(g_P16 + (size_t)node0 * 512 + col) =
                    __floats2half2_rn(acc[nt][0], acc[nt][1]);
            if (node1 < NN)
                *(half2*)(g_P16 + (size_t)node1 * 512 + col) =
                    __floats2half2_rn(acc[nt][2], acc[nt][3]);
        }
    }
}

// ---------------------------------------------------------------------------
// lstm_mma_kernel: CTA = 48 nodes, 12 warps (16x32 tiles); gates i, g, f, o.
// A (H-tile) fragments cached in registers across the 4 gates per step.
// ---------------------------------------------------------------------------
__global__ void __launch_bounds__(LTH, 1)
lstm_mma_kernel(const float* __restrict__ Xin,
                float* __restrict__ Xout,
                const int* __restrict__ src,
                const float* __restrict__ Whh,   // [512,128]
                const float* __restrict__ Wl,    // [outdim,128]
                const float* __restrict__ bl,    // [outdim]
                const float* __restrict__ Wr,    // [outdim,128]
                int outdim, int do_relu, int do_res)
{
    extern __shared__ char smc[];
    const uint32_t sb = smem_u32(smc);
    int* sSrc0 = (int*)(smc);
    int* sSrc1 = (int*)(smc + 512);

    const int tid  = threadIdx.x;
    const int wid  = tid >> 5;
    const int lane = tid & 31;
    const int g8   = lane >> 2;
    const int q    = lane & 3;
    const int m0   = (wid % 3) * 16;
    const int n0   = (wid / 3) * 32;
    const int nblk = blockIdx.x * MCTA;

    const uint32_t aLane = (m0 + (lane & 15)) * ROWSTR + ((lane >> 4) * 16);
    const uint32_t aH0   = sb + SM_H0 + aLane;
    const uint32_t aH1   = sb + SM_H1 + aLane;
    const uint32_t bOff4 = (n0 + (lane & 7) + ((lane >> 4) << 3)) * ROWSTR +
                           (((lane >> 3) & 1) * 16);

    // Whh fp32->fp16, pre-scaled per gate
    for (int idx = tid; idx < 512 * 64; idx += LTH) {
        int rg = idx >> 6, cp = idx & 63;
        int gate = rg >> 7, row = rg & 127, col = cp * 2;
        float sc = gate_scale(gate);
        float2 v = *(const float2*)(Whh + (size_t)rg * 128 + col);
        v.x *= sc; v.y *= sc;
        *(half2*)(smc + SM_W + gate * WTILE_B + row * ROWSTR + col * 2) =
            __float22half2_rn(v);
    }
    for (int idx = tid; idx < HTILE_B / 16; idx += LTH)
        ((uint4*)(smc + SM_H0))[idx] = make_uint4(0u, 0u, 0u, 0u);
    if (tid < MCTA) {
        int n = nblk + tid;
        sSrc0[tid] = (n < NN) ? __ldg(src + n * DEG) : 0;
    }
    __syncthreads();

    float c[4][4];
    #pragma unroll
    for (int nt = 0; nt < 4; nt++)
        #pragma unroll
        for (int e = 0; e < 4; e++) c[nt][e] = 0.0f;

    #pragma unroll 1
    for (int t = 0; t < DEG; t++) {
        const int* sCur   = (t & 1) ? sSrc1 : sSrc0;
        int*       sNext  = (t & 1) ? sSrc0 : sSrc1;
        const uint32_t aH = (t & 1) ? aH1 : aH0;
        char*      hNext  = (t & 1) ? (smc + SM_H0) : (smc + SM_H1);

        const int cq = n0 + q * 2;
        const __half* p0 = g_P16 + (size_t)sCur[m0 + g8]     * 512 + cq;
        const __half* p1 = g_P16 + (size_t)sCur[m0 + g8 + 8] * 512 + cq;

        uint32_t aF[8][4];
        lda_frags(aF, aH);   // H fragments: loaded once, used by all 4 gates

        float acc[4][4], tmp[4][4];

        // -- gate i (z/2): tmp = sigmoid --
        loadP(acc, p0, p1, 0 * 128);
        mma_tile16A(aF, sb + SM_W + 0 * WTILE_B + bOff4, acc);
        #pragma unroll
        for (int nt = 0; nt < 4; nt++)
            #pragma unroll
            for (int e = 0; e < 4; e++)
                tmp[nt][e] = fsig_pre(acc[nt][e]);

        // -- gate g (unscaled): tmp *= tanh(acc) --
        loadP(acc, p0, p1, 2 * 128);
        mma_tile16A(aF, sb + SM_W + 2 * WTILE_B + bOff4, acc);
        #pragma unroll
        for (int nt = 0; nt < 4; nt++)
            #pragma unroll
            for (int e = 0; e < 4; e++)
                tmp[nt][e] *= ftanh(acc[nt][e]);

        // -- gate f (z/2): c = sigmoid*c + tmp --
        loadP(acc, p0, p1, 1 * 128);
        mma_tile16A(aF, sb + SM_W + 1 * WTILE_B + bOff4, acc);
        #pragma unroll
        for (int nt = 0; nt < 4; nt++)
            #pragma unroll
            for (int e = 0; e < 4; e++)
                c[nt][e] = fmaf(fsig_pre(acc[nt][e]), c[nt][e], tmp[nt][e]);

        // -- gate o (z/2): raw half-pre-activation stays in acc --
        loadP(acc, p0, p1, 3 * 128);
        mma_tile16A(aF, sb + SM_W + 3 * WTILE_B + bOff4, acc);

        // h = sigmoid(o)*tanh(c) -> other H buffer
        {
            const int row = m0 + g8;
            #pragma unroll
            for (int nt = 0; nt < 4; nt++) {
                const int colb = (n0 + nt * 8 + q * 2) * 2;
                half2 h0 = __floats2half2_rn(
                    fsig_pre(acc[nt][0]) * ftanh(c[nt][0]),
                    fsig_pre(acc[nt][1]) * ftanh(c[nt][1]));
                half2 h1 = __floats2half2_rn(
                    fsig_pre(acc[nt][2]) * ftanh(c[nt][2]),
                    fsig_pre(acc[nt][3]) * ftanh(c[nt][3]));
                *(half2*)(hNext + row * ROWSTR + colb)       = h0;
                *(half2*)(hNext + (row + 8) * ROWSTR + colb) = h1;
            }
        }
        if (tid < MCTA && t + 1 < DEG) {
            int n = nblk + tid;
            sNext[tid] = (n < NN) ? __ldg(src + n * DEG + t + 1) : 0;
        }
        __syncthreads();
    }
    // final H in buffer H0 (DEG even)

    // ---- projections: out = H@Wl^T + bl + X@Wr^T (+res)(relu) --------------
    {
        const half2 z = __float2half2_rn(0.0f);
        for (int idx = tid; idx < 128 * 64; idx += LTH) {
            int row = idx >> 6, cp = idx & 63, col = cp * 2;
            half2 vl = z, vr = z;
            if (row < outdim) {
                vl = __float22half2_rn(*(const float2*)(Wl + (size_t)row * 128 + col));
                vr = __float22half2_rn(*(const float2*)(Wr + (size_t)row * 128 + col));
            }
            int off = row * ROWSTR + col * 2;
            *(half2*)(smc + SM_W + off)           = vl;
            *(half2*)(smc + SM_W + WTILE_B + off) = vr;
            if (row < MCTA) {
                int n = nblk + row; if (n >= NN) n = NN - 1;
                *(half2*)(smc + SM_W + 2 * WTILE_B + off) =
                    __float22half2_rn(*(const float2*)(Xin + (size_t)n * 128 + col));
            }
        }
    }
    __syncthreads();

    float acc[4][4];
    {
        const int node0 = nblk + m0 + g8, node1 = node0 + 8;
        #pragma unroll
        for (int nt = 0; nt < 4; nt++) {
            const int colp = n0 + nt * 8 + q * 2;
            float b0 = 0.f, b1 = 0.f;
            if (colp < outdim) { b0 = __ldg(bl + colp); b1 = __ldg(bl + colp + 1); }
            float x00 = 0.f, x01 = 0.f, x10 = 0.f, x11 = 0.f;
            if (do_res) {
                if (node0 < NN) {
                    float2 v = *(const float2*)(Xin + (size_t)node0 * 128 + colp);
                    x00 = v.x; x01 = v.y;
                }
                if (node1 < NN) {
                    float2 v = *(const float2*)(Xin + (size_t)node1 * 128 + colp);
                    x10 = v.x; x11 = v.y;
                }
            }
            acc[nt][0] = b0 + x00; acc[nt][1] = b1 + x01;
            acc[nt][2] = b0 + x10; acc[nt][3] = b1 + x11;
        }
    }

    {
        uint32_t aF[8][4];
        lda_frags(aF, aH0);                                      // H
        mma_tile16A(aF, sb + SM_W + 0 * WTILE_B + bOff4, acc);   // H @ Wl^T
        lda_frags(aF, sb + SM_W + 2 * WTILE_B + aLane);          // X
        mma_tile16A(aF, sb + SM_W + 1 * WTILE_B + bOff4, acc);   // X @ Wr^T
    }

    {
        const int node0 = nblk + m0 + g8, node1 = node0 + 8;
        #pragma unroll
        for (int nt = 0; nt < 4; nt++) {
            const int colp = n0 + nt * 8 + q * 2;
            if (colp >= outdim) continue;
            float v0 = acc[nt][0], v1 = acc[nt][1];
            float v2 = acc[nt][2], v3 = acc[nt][3];
            if (do_relu) {
                v0 = fmaxf(v0, 0.f); v1 = fmaxf(v1, 0.f);
                v2 = fmaxf(v2, 0.f); v3 = fmaxf(v3, 0.f);
            }
            if (node0 < NN)
                *(float2*)(Xout + (size_t)node0 * outdim + colp) = make_float2(v0, v1);
            if (node1 < NN)
                *(float2*)(Xout + (size_t)node1 * outdim + colp) = make_float2(v2, v3);
        }
    }
}

// ---------------------------------------------------------------------------
static void run_layer(const float* Xin, float* Xout, const int* src,
                      const float* Wih, const float* Whh,
                      const float* bih, const float* bhh,
                      const float* Wl, const float* bl, const float* Wr,
                      int outdim, int do_relu, int do_res)
{
    p_mma_kernel<<<NCTA2, LTH, SMEM_PM>>>(Xin, Wih, bih, bhh);
    lstm_mma_kernel<<<NCTA2, LTH, SMEM_L>>>(Xin, Xout, src, Whh, Wl, bl, Wr,
                                            outdim, do_relu, do_res);
}

extern "C" void kernel_launch(void* const* d_in, const int* in_sizes, int n_in,
                              void* d_out, int out_size)
{
    (void)in_sizes; (void)n_in; (void)out_size;
    const float* x     = (const float*)d_in[0];
    const int*   src   = (const int*)  d_in[1];
    const float* Wih   = (const float*)d_in[2];   // [4,512,128]
    const float* Whh   = (const float*)d_in[3];   // [4,512,128]
    const float* bih   = (const float*)d_in[4];   // [4,512]
    const float* bhh   = (const float*)d_in[5];   // [4,512]
    const float* Wl123 = (const float*)d_in[6];   // [3,128,128]
    const float* bl123 = (const float*)d_in[7];   // [3,128]
    const float* Wr123 = (const float*)d_in[8];   // [3,128,128]
    const float* Wl4   = (const float*)d_in[9];   // [64,128]
    const float* bl4   = (const float*)d_in[10];  // [64]
    const float* Wr4   = (const float*)d_in[11];  // [64,128]
    float*       out   = (float*)d_out;           // [N,64]

    cudaFuncSetAttribute(p_mma_kernel,
        cudaFuncAttributeMaxDynamicSharedMemorySize, (int)SMEM_PM);
    cudaFuncSetAttribute(lstm_mma_kernel,
        cudaFuncAttributeMaxDynamicSharedMemorySize, (int)SMEM_L);

    float *xa = nullptr, *xb = nullptr;
    cudaGetSymbolAddress((void**)&xa, g_XA);
    cudaGetSymbolAddress((void**)&xb, g_XB);

    run_layer(x,  xa, src, Wih + 0 * 512 * 128, Whh + 0 * 512 * 128,
              bih + 0 * 512, bhh + 0 * 512,
              Wl123 + 0 * 128 * 128, bl123 + 0 * 128, Wr123 + 0 * 128 * 128,
              128, 1, 0);
    run_layer(xa, xb, src, Wih + 1 * 512 * 128, Whh + 1 * 512 * 128,
              bih + 1 * 512, bhh + 1 * 512,
              Wl123 + 1 * 128 * 128, bl123 + 1 * 128, Wr123 + 1 * 128 * 128,
              128, 1, 1);
    run_layer(xb, xa, src, Wih + 2 * 512 * 128, Whh + 2 * 512 * 128,
              bih + 2 * 512, bhh + 2 * 512,
              Wl123 + 2 * 128 * 128, bl123 + 2 * 128, Wr123 + 2 * 128 * 128,
              128, 1, 1);
    run_layer(xa, out, src, Wih + 3 * 512 * 128, Whh + 3 * 512 * 128,
              bih + 3 * 512, bhh + 3 * 512,
              Wl4, bl4, Wr4,
              64, 0, 0);
}